// round 1
// baseline (speedup 1.0000x reference)
#include <cuda_runtime.h>
#include <cuda_bf16.h>
#include <math.h>

#define VV 4
#define NN 1536
#define DD 256
#define TOPK 32
#define NHEADS 4
#define HD 64
#define ROWS_TOT (VV*NN)   // 6144

// ---------------- scratch (device globals; no allocation allowed) ----------
__device__ float g_qkv[VV*NN*3*DD];        // 18.9 MB
__device__ float g_o[VV*NN*DD];            // 6.3 MB
__device__ float g_aligned[VV*NN*DD];
__device__ float g_Qn[VV*NN*DD];
__device__ float g_Kn[VV*NN*DD];
__device__ float g_Vn[VV*NN*DD];
__device__ float g_part[VV*8*DD];
__device__ float g_vmean[VV*DD];
__device__ int   g_topk[VV*VV*NN*TOPK];    // 3 MB

// ---------------- generic NT GEMM: C[m,n] = sum_k A[m,k]*B[n,k] (+bias) ----
// BM=BN=128, BK=16, 256 threads, 8x8 per thread.
// EPI==1: C = alpha_v*(gemm+bias) + (1-alpha_v)*Hx   (v = row / viewRows)
#define BM 128
#define BN 128
#define BK 16

template<int EPI>
__global__ __launch_bounds__(256)
void gemm_nt(const float* __restrict__ A, const float* __restrict__ B,
             const float* __restrict__ bias, float* __restrict__ Cc,
             int M, int Ncols, int K,
             long sA, long sB, long sC,
             const float* __restrict__ Hx, const float* __restrict__ alphas,
             int viewRows)
{
    int bz = blockIdx.z;
    A  += (long)bz * sA;
    B  += (long)bz * sB;
    Cc += (long)bz * sC;

    __shared__ __align__(16) float As[BK][BM];
    __shared__ __align__(16) float Bs[BK][BN];

    const int tid = threadIdx.x;
    const int tx = tid & 15;      // 0..15 -> N direction
    const int ty = tid >> 4;      // 0..15 -> M direction
    const int m0 = blockIdx.y * BM;
    const int n0 = blockIdx.x * BN;

    float acc[8][8];
#pragma unroll
    for (int i = 0; i < 8; i++)
#pragma unroll
        for (int j = 0; j < 8; j++) acc[i][j] = 0.f;

    for (int k0 = 0; k0 < K; k0 += BK) {
        // load tiles: 128x16 floats each = 512 float4 -> 2 per thread
#pragma unroll
        for (int ld = 0; ld < 2; ld++) {
            int lin = tid + ld * 256;
            int row = lin >> 2;
            int c4  = lin & 3;
            float4 av = *reinterpret_cast<const float4*>(
                &A[(long)(m0 + row) * K + k0 + c4 * 4]);
            As[c4*4+0][row] = av.x; As[c4*4+1][row] = av.y;
            As[c4*4+2][row] = av.z; As[c4*4+3][row] = av.w;
            float4 bv = *reinterpret_cast<const float4*>(
                &B[(long)(n0 + row) * K + k0 + c4 * 4]);
            Bs[c4*4+0][row] = bv.x; Bs[c4*4+1][row] = bv.y;
            Bs[c4*4+2][row] = bv.z; Bs[c4*4+3][row] = bv.w;
        }
        __syncthreads();

#pragma unroll
        for (int kk = 0; kk < BK; kk++) {
            float4 a0 = *reinterpret_cast<float4*>(&As[kk][ty*8]);
            float4 a1 = *reinterpret_cast<float4*>(&As[kk][ty*8+4]);
            float4 b0 = *reinterpret_cast<float4*>(&Bs[kk][tx*8]);
            float4 b1 = *reinterpret_cast<float4*>(&Bs[kk][tx*8+4]);
            float a[8] = {a0.x,a0.y,a0.z,a0.w,a1.x,a1.y,a1.z,a1.w};
            float b[8] = {b0.x,b0.y,b0.z,b0.w,b1.x,b1.y,b1.z,b1.w};
#pragma unroll
            for (int i = 0; i < 8; i++)
#pragma unroll
                for (int j = 0; j < 8; j++)
                    acc[i][j] = fmaf(a[i], b[j], acc[i][j]);
        }
        __syncthreads();
    }

#pragma unroll
    for (int i = 0; i < 8; i++) {
        int r = m0 + ty*8 + i;
#pragma unroll
        for (int j = 0; j < 8; j++) {
            int c = n0 + tx*8 + j;
            float v = acc[i][j] + (bias ? bias[c] : 0.f);
            long off = (long)r * Ncols + c;
            if (EPI == 1) {
                float a = alphas[r / viewRows];
                v = a * v + (1.f - a) * Hx[off];
            }
            Cc[off] = v;
        }
    }
}

// ---------------- tiny attention over views: one warp per (n,h) ------------
__global__ __launch_bounds__(256)
void view_attn(const float* __restrict__ qkv, float* __restrict__ o)
{
    int gw = blockIdx.x * 8 + (threadIdx.x >> 5);
    if (gw >= NN * NHEADS) return;
    int lane = threadIdx.x & 31;
    int n = gw >> 2;        // / NHEADS
    int h = gw & 3;

    float qf[VV][2], kf[VV][2], vf[VV][2];
#pragma unroll
    for (int l = 0; l < VV; l++) {
        long base = ((long)(l * NN + n)) * (3 * DD) + h * HD;
        qf[l][0] = qkv[base + lane];          qf[l][1] = qkv[base + lane + 32];
        kf[l][0] = qkv[base + DD + lane];     kf[l][1] = qkv[base + DD + lane + 32];
        vf[l][0] = qkv[base + 2*DD + lane];   vf[l][1] = qkv[base + 2*DD + lane + 32];
    }

    float s[VV][VV];
#pragma unroll
    for (int l = 0; l < VV; l++)
#pragma unroll
        for (int m = 0; m < VV; m++) {
            float p = qf[l][0]*kf[m][0] + qf[l][1]*kf[m][1];
#pragma unroll
            for (int off = 16; off; off >>= 1)
                p += __shfl_xor_sync(0xFFFFFFFFu, p, off);
            s[l][m] = p * 0.125f;   // 1/sqrt(64)
        }

#pragma unroll
    for (int l = 0; l < VV; l++) {
        float mx = fmaxf(fmaxf(s[l][0], s[l][1]), fmaxf(s[l][2], s[l][3]));
        float e0 = __expf(s[l][0]-mx), e1 = __expf(s[l][1]-mx),
              e2 = __expf(s[l][2]-mx), e3 = __expf(s[l][3]-mx);
        float inv = 1.f / (e0+e1+e2+e3);
        float o0 = (e0*vf[0][0] + e1*vf[1][0] + e2*vf[2][0] + e3*vf[3][0]) * inv;
        float o1 = (e0*vf[0][1] + e1*vf[1][1] + e2*vf[2][1] + e3*vf[3][1]) * inv;
        long base = ((long)(l * NN + n)) * DD + h * HD;
        o[base + lane]      = o0;
        o[base + lane + 32] = o1;
    }
}

// ---------------- top-32 indices per (v,q,n) row of C -----------------------
__global__ __launch_bounds__(256)
void topk_kernel(const float* __restrict__ C, int* __restrict__ outIdx)
{
    int vq = blockIdx.y;
    int v = vq >> 2, q = vq & 3;
    if (v == q) return;                 // masked by (1 - eye)
    int n = blockIdx.x;
    int t = threadIdx.x;

    __shared__ float vals[NN];
    __shared__ float rmax[256];
    __shared__ int   rIdx[256];

    const float* row = C + ((long)vq * NN + n) * (long)NN;
    for (int m = t; m < NN; m += 256) vals[m] = row[m];
    __syncthreads();

    int* outp = outIdx + ((long)vq * NN + n) * TOPK;
    for (int it = 0; it < TOPK; it++) {
        float bv = -1e38f; int bi = 0;
        for (int m = t; m < NN; m += 256) {
            float x = vals[m];
            if (x > bv) { bv = x; bi = m; }
        }
        rmax[t] = bv; rIdx[t] = bi;
        __syncthreads();
#pragma unroll
        for (int s2 = 128; s2; s2 >>= 1) {
            if (t < s2) {
                float ov = rmax[t+s2]; int oi = rIdx[t+s2];
                if (ov > rmax[t] || (ov == rmax[t] && oi < rIdx[t])) {
                    rmax[t] = ov; rIdx[t] = oi;
                }
            }
            __syncthreads();
        }
        if (t == 0) { outp[it] = rIdx[0]; vals[rIdx[0]] = -1e38f; }
        __syncthreads();
    }
}

// ---------------- Vn mean over tokens (p==q uniform-softmax term) ----------
__global__ void vmean_partial(const float* __restrict__ Vn, float* __restrict__ part)
{
    int v = blockIdx.x, chunk = blockIdx.y, t = threadIdx.x;
    float s = 0.f;
    int nbeg = chunk * (NN/8), nend = nbeg + (NN/8);
    for (int n = nbeg; n < nend; n++)
        s += Vn[((long)v * NN + n) * DD + t];
    part[(v*8 + chunk) * DD + t] = s;
}
__global__ void vmean_final(const float* __restrict__ part, float* __restrict__ vmean)
{
    int v = blockIdx.x, t = threadIdx.x;
    float s = 0.f;
#pragma unroll
    for (int c = 0; c < 8; c++) s += part[(v*8 + c) * DD + t];
    vmean[v * DD + t] = s * (1.0f / NN);
}

// ---------------- sparse neighbor attention + final fuse -------------------
__global__ __launch_bounds__(256)
void nbr_out(const float* __restrict__ Qn, const float* __restrict__ Kn,
             const float* __restrict__ Vn, const float* __restrict__ vmean,
             const int* __restrict__ topk, const float* __restrict__ aligned,
             const float* __restrict__ Hin,
             const float* __restrict__ alpha_align, const float* __restrict__ beta,
             float* __restrict__ out)
{
    int pn = blockIdx.x;
    int p = pn / NN, n = pn % NN;
    int t = threadIdx.x, lane = t & 31, wid = t >> 5;

    __shared__ float Qrow[DD];
    __shared__ float sdots[TOPK];
    __shared__ int   sidx[TOPK];

    long rowOff = (long)pn * DD;
    Qrow[t] = Qn[rowOff + t];
    float acc = vmean[p * DD + t];   // q==p: fully-masked softmax -> uniform mean
    __syncthreads();

    for (int q = 0; q < VV; q++) {
        if (q == p) continue;
        if (t < TOPK)
            sidx[t] = topk[(((long)(p*VV + q)) * NN + n) * TOPK + t];
        __syncthreads();

        // 32 dot products over D=256: warp w handles j = w, w+8, ...
        for (int j = wid; j < TOPK; j += 8) {
            const float* krow = Kn + ((long)q * NN + sidx[j]) * DD;
            float4 qa = *reinterpret_cast<const float4*>(&Qrow[lane*8]);
            float4 qb = *reinterpret_cast<const float4*>(&Qrow[lane*8+4]);
            float4 ka = *reinterpret_cast<const float4*>(&krow[lane*8]);
            float4 kb = *reinterpret_cast<const float4*>(&krow[lane*8+4]);
            float psum = qa.x*ka.x + qa.y*ka.y + qa.z*ka.z + qa.w*ka.w
                       + qb.x*kb.x + qb.y*kb.y + qb.z*kb.z + qb.w*kb.w;
#pragma unroll
            for (int off = 16; off; off >>= 1)
                psum += __shfl_xor_sync(0xFFFFFFFFu, psum, off);
            if (lane == 0) sdots[j] = psum * 0.0625f;   // 1/sqrt(256)
        }
        __syncthreads();

        if (wid == 0) {   // softmax over 32 in one warp
            float x = sdots[lane];
            float mx = x;
#pragma unroll
            for (int off = 16; off; off >>= 1)
                mx = fmaxf(mx, __shfl_xor_sync(0xFFFFFFFFu, mx, off));
            float e = __expf(x - mx);
            float sm = e;
#pragma unroll
            for (int off = 16; off; off >>= 1)
                sm += __shfl_xor_sync(0xFFFFFFFFu, sm, off);
            sdots[lane] = e / sm;
        }
        __syncthreads();

#pragma unroll 8
        for (int j = 0; j < TOPK; j++)
            acc = fmaf(sdots[j], Vn[((long)q * NN + sidx[j]) * DD + t], acc);
        __syncthreads();
    }

    float aa = 1.f / (1.f + __expf(-alpha_align[0]));
    float bb = 1.f / (1.f + __expf(-beta[0]));
    float al = aligned[rowOff + t];
    float f  = fmaxf(aa * al + (1.f - aa) * acc, 0.f);
    out[rowOff + t] = bb * Hin[rowOff + t] + (1.f - bb) * f;
}

// ---------------- launch ----------------------------------------------------
extern "C" void kernel_launch(void* const* d_in, const int* in_sizes, int n_in,
                              void* d_out, int out_size)
{
    const float* H      = (const float*)d_in[0];
    const float* C      = (const float*)d_in[1];
    const float* WQ     = (const float*)d_in[2];
    const float* WK     = (const float*)d_in[3];
    const float* WV     = (const float*)d_in[4];
    const float* ipw    = (const float*)d_in[5];
    const float* ipb    = (const float*)d_in[6];
    const float* ow     = (const float*)d_in[7];
    const float* ob     = (const float*)d_in[8];
    const float* alphas = (const float*)d_in[9];
    const float* aal    = (const float*)d_in[10];
    const float* bet    = (const float*)d_in[11];
    float* out = (float*)d_out;

    float *p_qkv, *p_o, *p_aligned, *p_Qn, *p_Kn, *p_Vn, *p_part, *p_vmean;
    int* p_tk;
    cudaGetSymbolAddress((void**)&p_qkv, g_qkv);
    cudaGetSymbolAddress((void**)&p_o, g_o);
    cudaGetSymbolAddress((void**)&p_aligned, g_aligned);
    cudaGetSymbolAddress((void**)&p_Qn, g_Qn);
    cudaGetSymbolAddress((void**)&p_Kn, g_Kn);
    cudaGetSymbolAddress((void**)&p_Vn, g_Vn);
    cudaGetSymbolAddress((void**)&p_part, g_part);
    cudaGetSymbolAddress((void**)&p_vmean, g_vmean);
    cudaGetSymbolAddress((void**)&p_tk, g_topk);

    // 1) qkv = H @ in_proj_w^T + b     (6144 x 768 x 256)
    gemm_nt<0><<<dim3(768/BN, ROWS_TOT/BM, 1), 256>>>(
        H, ipw, ipb, p_qkv, ROWS_TOT, 3*DD, DD, 0, 0, 0, nullptr, nullptr, NN);

    // top-k indices of C (independent of the rest; 151MB read)
    topk_kernel<<<dim3(NN, VV*VV), 256>>>(C, p_tk);

    // 2) tiny 4x4 attention over views per (token, head)
    view_attn<<<(NN*NHEADS)/8, 256>>>(p_qkv, p_o);

    // 3) fusion = o @ out_w^T + b; aligned = a*fusion + (1-a)*H  (fused epilogue)
    gemm_nt<1><<<dim3(DD/BN, ROWS_TOT/BM, 1), 256>>>(
        p_o, ow, ob, p_aligned, ROWS_TOT, DD, DD, 0, 0, 0, H, alphas, NN);

    // 4) per-view Qn/Kn/Vn = aligned @ W[v]^T   (batched over v)
    long sAB = (long)NN * DD, sW = (long)DD * DD;
    gemm_nt<0><<<dim3(DD/BN, NN/BM, VV), 256>>>(
        p_aligned, WQ, nullptr, p_Qn, NN, DD, DD, sAB, sW, sAB, nullptr, nullptr, NN);
    gemm_nt<0><<<dim3(DD/BN, NN/BM, VV), 256>>>(
        p_aligned, WK, nullptr, p_Kn, NN, DD, DD, sAB, sW, sAB, nullptr, nullptr, NN);
    gemm_nt<0><<<dim3(DD/BN, NN/BM, VV), 256>>>(
        p_aligned, WV, nullptr, p_Vn, NN, DD, DD, sAB, sW, sAB, nullptr, nullptr, NN);

    // 5) mean of Vn over tokens (p==q uniform softmax term), deterministic 2-pass
    vmean_partial<<<dim3(VV, 8), 256>>>(p_Vn, p_part);
    vmean_final<<<VV, 256>>>(p_part, p_vmean);

    // 6) sparse neighbor attention + final relu/fuse
    nbr_out<<<ROWS_TOT, 256>>>(p_Qn, p_Kn, p_Vn, p_vmean, p_tk,
                               p_aligned, H, aal, bet, out);
}

// round 2
// speedup vs baseline: 2.4340x; 2.4340x over previous
#include <cuda_runtime.h>
#include <cuda_fp16.h>
#include <math.h>

#define VV 4
#define NN 1536
#define DD 256
#define TOPK 32
#define NHEADS 4
#define HD 64
#define ROWS_TOT (VV*NN)   // 6144
#define CAP 256            // per-warp candidate buffer for top-k

// ---------------- scratch (device globals; no allocation allowed) ----------
__device__ float  g_qkv[VV*NN*3*DD];
__device__ float  g_o[VV*NN*DD];
__device__ float  g_aligned[VV*NN*DD];
__device__ float  g_Qn[VV*NN*DD];
__device__ __half g_Kh[VV*NN*DD];
__device__ __half g_Vh[VV*NN*DD];
__device__ float  g_part[VV*8*DD];
__device__ float  g_vmean[VV*DD];
__device__ int    g_topk[VV*VV*NN*TOPK];

// ---------------- shared SGEMM core: 128x128x16, 256 thr, 8x8/thread -------
#define BM 128
#define BN 128
#define BK 16

__device__ __forceinline__ void sgemm_core(
    const float* __restrict__ A, const float* __restrict__ B, int K,
    float (&As)[BK][BM], float (&Bs)[BK][BN], float (&acc)[8][8],
    int m0, int n0, int tid)
{
    const int tx = tid & 15;
    const int ty = tid >> 4;

    for (int k0 = 0; k0 < K; k0 += BK) {
#pragma unroll
        for (int ld = 0; ld < 2; ld++) {
            int lin = tid + ld * 256;
            int row = lin >> 2;
            int c4  = lin & 3;
            float4 av = *reinterpret_cast<const float4*>(
                &A[(long)(m0 + row) * K + k0 + c4 * 4]);
            As[c4*4+0][row] = av.x; As[c4*4+1][row] = av.y;
            As[c4*4+2][row] = av.z; As[c4*4+3][row] = av.w;
            float4 bv = *reinterpret_cast<const float4*>(
                &B[(long)(n0 + row) * K + k0 + c4 * 4]);
            Bs[c4*4+0][row] = bv.x; Bs[c4*4+1][row] = bv.y;
            Bs[c4*4+2][row] = bv.z; Bs[c4*4+3][row] = bv.w;
        }
        __syncthreads();

#pragma unroll
        for (int kk = 0; kk < BK; kk++) {
            float4 a0 = *reinterpret_cast<float4*>(&As[kk][ty*8]);
            float4 a1 = *reinterpret_cast<float4*>(&As[kk][ty*8+4]);
            float4 b0 = *reinterpret_cast<float4*>(&Bs[kk][tx*8]);
            float4 b1 = *reinterpret_cast<float4*>(&Bs[kk][tx*8+4]);
            float a[8] = {a0.x,a0.y,a0.z,a0.w,a1.x,a1.y,a1.z,a1.w};
            float b[8] = {b0.x,b0.y,b0.z,b0.w,b1.x,b1.y,b1.z,b1.w};
#pragma unroll
            for (int i = 0; i < 8; i++)
#pragma unroll
                for (int j = 0; j < 8; j++)
                    acc[i][j] = fmaf(a[i], b[j], acc[i][j]);
        }
        __syncthreads();
    }
}

// 1) qkv = H @ ipw^T + bias   (6144 x 768 x 256)
__global__ __launch_bounds__(256)
void gemm_qkv(const float* __restrict__ A, const float* __restrict__ B,
              const float* __restrict__ bias, float* __restrict__ Cc, int K)
{
    __shared__ __align__(16) float As[BK][BM];
    __shared__ __align__(16) float Bs[BK][BN];
    float acc[8][8];
#pragma unroll
    for (int i = 0; i < 8; i++)
#pragma unroll
        for (int j = 0; j < 8; j++) acc[i][j] = 0.f;

    const int tid = threadIdx.x;
    const int m0 = blockIdx.y * BM, n0 = blockIdx.x * BN;
    sgemm_core(A, B, K, As, Bs, acc, m0, n0, tid);

    const int tx = tid & 15, ty = tid >> 4;
#pragma unroll
    for (int i = 0; i < 8; i++) {
        int r = m0 + ty*8 + i;
#pragma unroll
        for (int j = 0; j < 8; j++) {
            int c = n0 + tx*8 + j;
            Cc[(long)r * (3*DD) + c] = acc[i][j] + bias[c];
        }
    }
}

// 3) aligned = a*(o @ ow^T + ob) + (1-a)*H
__global__ __launch_bounds__(256)
void gemm_out(const float* __restrict__ A, const float* __restrict__ B,
              const float* __restrict__ bias, float* __restrict__ Cc,
              const float* __restrict__ Hx, const float* __restrict__ alphas, int K)
{
    __shared__ __align__(16) float As[BK][BM];
    __shared__ __align__(16) float Bs[BK][BN];
    float acc[8][8];
#pragma unroll
    for (int i = 0; i < 8; i++)
#pragma unroll
        for (int j = 0; j < 8; j++) acc[i][j] = 0.f;

    const int tid = threadIdx.x;
    const int m0 = blockIdx.y * BM, n0 = blockIdx.x * BN;
    sgemm_core(A, B, K, As, Bs, acc, m0, n0, tid);

    const int tx = tid & 15, ty = tid >> 4;
#pragma unroll
    for (int i = 0; i < 8; i++) {
        int r = m0 + ty*8 + i;
        float a = alphas[r / NN];
#pragma unroll
        for (int j = 0; j < 8; j++) {
            int c = n0 + tx*8 + j;
            long off = (long)r * DD + c;
            Cc[off] = a * (acc[i][j] + bias[c]) + (1.f - a) * Hx[off];
        }
    }
}

// 4) fused per-view Qn/Kn/Vn: z = which*4 + v, which in {0(Q),1(K),2(V)}
//    Q -> fp32, K/V -> fp16
__global__ __launch_bounds__(256)
void gemm_qkvn(const float* __restrict__ aligned,
               const float* __restrict__ WQ, const float* __restrict__ WK,
               const float* __restrict__ WV,
               float* __restrict__ Qn, __half* __restrict__ Kh,
               __half* __restrict__ Vh, int K)
{
    int z = blockIdx.z;
    int which = z >> 2, v = z & 3;
    const float* A = aligned + (long)v * NN * DD;
    const float* B = (which == 0 ? WQ : which == 1 ? WK : WV) + (long)v * DD * DD;

    __shared__ __align__(16) float As[BK][BM];
    __shared__ __align__(16) float Bs[BK][BN];
    float acc[8][8];
#pragma unroll
    for (int i = 0; i < 8; i++)
#pragma unroll
        for (int j = 0; j < 8; j++) acc[i][j] = 0.f;

    const int tid = threadIdx.x;
    const int m0 = blockIdx.y * BM, n0 = blockIdx.x * BN;
    sgemm_core(A, B, K, As, Bs, acc, m0, n0, tid);

    const int tx = tid & 15, ty = tid >> 4;
    long vbase = (long)v * NN * DD;
#pragma unroll
    for (int i = 0; i < 8; i++) {
        int r = m0 + ty*8 + i;
#pragma unroll
        for (int j = 0; j < 8; j++) {
            int c = n0 + tx*8 + j;
            long off = vbase + (long)r * DD + c;
            if (which == 0)      Qn[off] = acc[i][j];
            else if (which == 1) Kh[off] = __float2half_rn(acc[i][j]);
            else                 Vh[off] = __float2half_rn(acc[i][j]);
        }
    }
}

// ---------------- tiny attention over views: one warp per (n,h) ------------
__global__ __launch_bounds__(256)
void view_attn(const float* __restrict__ qkv, float* __restrict__ o)
{
    int gw = blockIdx.x * 8 + (threadIdx.x >> 5);
    if (gw >= NN * NHEADS) return;
    int lane = threadIdx.x & 31;
    int n = gw >> 2;
    int h = gw & 3;

    float qf[VV][2], kf[VV][2], vf[VV][2];
#pragma unroll
    for (int l = 0; l < VV; l++) {
        long base = ((long)(l * NN + n)) * (3 * DD) + h * HD;
        qf[l][0] = qkv[base + lane];          qf[l][1] = qkv[base + lane + 32];
        kf[l][0] = qkv[base + DD + lane];     kf[l][1] = qkv[base + DD + lane + 32];
        vf[l][0] = qkv[base + 2*DD + lane];   vf[l][1] = qkv[base + 2*DD + lane + 32];
    }

    float s[VV][VV];
#pragma unroll
    for (int l = 0; l < VV; l++)
#pragma unroll
        for (int m = 0; m < VV; m++) {
            float p = qf[l][0]*kf[m][0] + qf[l][1]*kf[m][1];
#pragma unroll
            for (int off = 16; off; off >>= 1)
                p += __shfl_xor_sync(0xFFFFFFFFu, p, off);
            s[l][m] = p * 0.125f;
        }

#pragma unroll
    for (int l = 0; l < VV; l++) {
        float mx = fmaxf(fmaxf(s[l][0], s[l][1]), fmaxf(s[l][2], s[l][3]));
        float e0 = __expf(s[l][0]-mx), e1 = __expf(s[l][1]-mx),
              e2 = __expf(s[l][2]-mx), e3 = __expf(s[l][3]-mx);
        float inv = 1.f / (e0+e1+e2+e3);
        float o0 = (e0*vf[0][0] + e1*vf[1][0] + e2*vf[2][0] + e3*vf[3][0]) * inv;
        float o1 = (e0*vf[0][1] + e1*vf[1][1] + e2*vf[2][1] + e3*vf[3][1]) * inv;
        long base = ((long)(l * NN + n)) * DD + h * HD;
        o[base + lane]      = o0;
        o[base + lane + 32] = o1;
    }
}

// ---------------- fast top-32 per off-diagonal (v,q,n) row of C -------------
// One warp per row: threshold compaction (uniform[0,1) data => t=0.95 keeps
// ~77 of 1536; P(fail) ~ 1e-7/row with t=0.9 retry), then 32 warp argmax
// iterations over 64-bit keys (valbits<<32 | ~idx) = exact jax top_k order.
__global__ __launch_bounds__(256)
void topk_fast(const float* __restrict__ C, int* __restrict__ outIdx)
{
    __shared__ unsigned long long buf[8][CAP];
    const unsigned FULL = 0xFFFFFFFFu;
    int wid = threadIdx.x >> 5, lane = threadIdx.x & 31;
    int gw = blockIdx.x * 8 + wid;            // 0 .. 18431
    int pair = gw / NN, n = gw - pair * NN;
    int v = pair / 3, r3 = pair - v * 3;
    int q = r3 + (r3 >= v ? 1 : 0);

    const float* row = C + ((long)(v*4 + q) * NN + n) * (long)NN;
    int* outp = outIdx + ((long)(v*4 + q) * NN + n) * TOPK;
    unsigned long long* wbuf = buf[wid];

    int cnt = 0;
    float thr = 0.95f;
#pragma unroll 1
    for (int att = 0; att < 2; att++) {
        cnt = 0;
#pragma unroll 1
        for (int i = lane; i < NN; i += 32) {
            float x = row[i];
            bool p = x > thr;
            unsigned m = __ballot_sync(FULL, p);
            if (p) {
                int pos = cnt + __popc(m & ((1u << lane) - 1u));
                if (pos < CAP)
                    wbuf[pos] = (((unsigned long long)__float_as_uint(x)) << 32)
                              | (unsigned)(0xFFFFFFFFu - i);
            }
            cnt += __popc(m);
        }
        if (cnt >= TOPK && cnt <= CAP) break;
        thr = 0.90f;
    }

    if (cnt < TOPK || cnt > CAP) {
        // fully-general exact fallback (never taken for uniform data):
        // repeated warp argmax over the gmem row with monotonic key transform
        unsigned long long prev = 0xFFFFFFFFFFFFFFFFull;
        for (int j = 0; j < TOPK; j++) {
            unsigned long long best = 0;
            for (int i = lane; i < NN; i += 32) {
                unsigned b = __float_as_uint(row[i]);
                unsigned key32 = (b & 0x80000000u) ? ~b : (b | 0x80000000u);
                unsigned long long k =
                    (((unsigned long long)key32) << 32) | (unsigned)(0xFFFFFFFFu - i);
                if (k < prev && k > best) best = k;
            }
#pragma unroll
            for (int off = 16; off; off >>= 1) {
                unsigned long long o = __shfl_xor_sync(FULL, best, off);
                if (o > best) best = o;
            }
            if (lane == 0) outp[j] = (int)(0xFFFFFFFFu - (unsigned)best);
            prev = best;
        }
        return;
    }

    // register-resident selection of top-32 among cnt (<=CAP) candidates
    const int SL = CAP / 32;   // 8
    unsigned long long c[SL];
#pragma unroll
    for (int k = 0; k < SL; k++) {
        int j = lane + 32 * k;
        c[k] = (j < cnt) ? wbuf[j] : 0ull;
    }
    unsigned long long lmax = 0; int lslot = 0;
#pragma unroll
    for (int k = 0; k < SL; k++) if (c[k] > lmax) { lmax = c[k]; lslot = k; }

#pragma unroll 1
    for (int j = 0; j < TOPK; j++) {
        unsigned long long best = lmax;
#pragma unroll
        for (int off = 16; off; off >>= 1) {
            unsigned long long o = __shfl_xor_sync(FULL, best, off);
            if (o > best) best = o;
        }
        if (lmax == best && best != 0ull) {   // unique owner (idx in key)
            outp[j] = (int)(0xFFFFFFFFu - (unsigned)best);
            c[lslot] = 0ull;
            lmax = 0; lslot = 0;
#pragma unroll
            for (int k = 0; k < SL; k++) if (c[k] > lmax) { lmax = c[k]; lslot = k; }
        }
    }
}

// ---------------- Vn mean over tokens (p==q uniform-softmax term) ----------
__global__ void vmean_partial(const __half* __restrict__ Vh, float* __restrict__ part)
{
    int v = blockIdx.x, chunk = blockIdx.y, t = threadIdx.x;
    float s = 0.f;
    int nbeg = chunk * (NN/8), nend = nbeg + (NN/8);
    for (int n = nbeg; n < nend; n++)
        s += __half2float(Vh[((long)v * NN + n) * DD + t]);
    part[(v*8 + chunk) * DD + t] = s;
}
__global__ void vmean_final(const float* __restrict__ part, float* __restrict__ vmean)
{
    int v = blockIdx.x, t = threadIdx.x;
    float s = 0.f;
#pragma unroll
    for (int c = 0; c < 8; c++) s += part[(v*8 + c) * DD + t];
    vmean[v * DD + t] = s * (1.0f / NN);
}

// ---------------- sparse neighbor attention + final fuse -------------------
__global__ __launch_bounds__(256)
void nbr_out(const float* __restrict__ Qn, const __half* __restrict__ Kh,
             const __half* __restrict__ Vh, const float* __restrict__ vmean,
             const int* __restrict__ topk, const float* __restrict__ aligned,
             const float* __restrict__ Hin,
             const float* __restrict__ alpha_align, const float* __restrict__ beta,
             float* __restrict__ out)
{
    int pn = blockIdx.x;
    int p = pn / NN, n = pn % NN;
    int t = threadIdx.x, lane = t & 31, wid = t >> 5;

    __shared__ float Qrow[DD];
    __shared__ float sdots[TOPK];
    __shared__ int   sidx[TOPK];

    long rowOff = (long)pn * DD;
    Qrow[t] = Qn[rowOff + t];
    float acc = vmean[p * DD + t];   // q==p: fully-masked softmax -> uniform mean
    __syncthreads();

    for (int q = 0; q < VV; q++) {
        if (q == p) continue;
        if (t < TOPK)
            sidx[t] = topk[(((long)(p*VV + q)) * NN + n) * TOPK + t];
        __syncthreads();

        for (int j = wid; j < TOPK; j += 8) {
            const __half* krow = Kh + ((long)q * NN + sidx[j]) * DD;
            uint4 kv = *reinterpret_cast<const uint4*>(krow + lane * 8);
            float2 k0 = __half22float2(*reinterpret_cast<__half2*>(&kv.x));
            float2 k1 = __half22float2(*reinterpret_cast<__half2*>(&kv.y));
            float2 k2 = __half22float2(*reinterpret_cast<__half2*>(&kv.z));
            float2 k3 = __half22float2(*reinterpret_cast<__half2*>(&kv.w));
            float4 qa = *reinterpret_cast<const float4*>(&Qrow[lane*8]);
            float4 qb = *reinterpret_cast<const float4*>(&Qrow[lane*8+4]);
            float psum = qa.x*k0.x + qa.y*k0.y + qa.z*k1.x + qa.w*k1.y
                       + qb.x*k2.x + qb.y*k2.y + qb.z*k3.x + qb.w*k3.y;
#pragma unroll
            for (int off = 16; off; off >>= 1)
                psum += __shfl_xor_sync(0xFFFFFFFFu, psum, off);
            if (lane == 0) sdots[j] = psum * 0.0625f;
        }
        __syncthreads();

        if (wid == 0) {
            float x = sdots[lane];
            float mx = x;
#pragma unroll
            for (int off = 16; off; off >>= 1)
                mx = fmaxf(mx, __shfl_xor_sync(0xFFFFFFFFu, mx, off));
            float e = __expf(x - mx);
            float sm = e;
#pragma unroll
            for (int off = 16; off; off >>= 1)
                sm += __shfl_xor_sync(0xFFFFFFFFu, sm, off);
            sdots[lane] = e / sm;
        }
        __syncthreads();

#pragma unroll 8
        for (int j = 0; j < TOPK; j++)
            acc = fmaf(sdots[j],
                       __half2float(Vh[((long)q * NN + sidx[j]) * DD + t]), acc);
        __syncthreads();
    }

    float aa = 1.f / (1.f + __expf(-alpha_align[0]));
    float bb = 1.f / (1.f + __expf(-beta[0]));
    float al = aligned[rowOff + t];
    float f  = fmaxf(aa * al + (1.f - aa) * acc, 0.f);
    out[rowOff + t] = bb * Hin[rowOff + t] + (1.f - bb) * f;
}

// ---------------- launch ----------------------------------------------------
extern "C" void kernel_launch(void* const* d_in, const int* in_sizes, int n_in,
                              void* d_out, int out_size)
{
    const float* H      = (const float*)d_in[0];
    const float* C      = (const float*)d_in[1];
    const float* WQ     = (const float*)d_in[2];
    const float* WK     = (const float*)d_in[3];
    const float* WV     = (const float*)d_in[4];
    const float* ipw    = (const float*)d_in[5];
    const float* ipb    = (const float*)d_in[6];
    const float* ow     = (const float*)d_in[7];
    const float* ob     = (const float*)d_in[8];
    const float* alphas = (const float*)d_in[9];
    const float* aal    = (const float*)d_in[10];
    const float* bet    = (const float*)d_in[11];
    float* out = (float*)d_out;

    float *p_qkv, *p_o, *p_aligned, *p_Qn, *p_part, *p_vmean;
    __half *p_Kh, *p_Vh;
    int* p_tk;
    cudaGetSymbolAddress((void**)&p_qkv, g_qkv);
    cudaGetSymbolAddress((void**)&p_o, g_o);
    cudaGetSymbolAddress((void**)&p_aligned, g_aligned);
    cudaGetSymbolAddress((void**)&p_Qn, g_Qn);
    cudaGetSymbolAddress((void**)&p_Kh, g_Kh);
    cudaGetSymbolAddress((void**)&p_Vh, g_Vh);
    cudaGetSymbolAddress((void**)&p_part, g_part);
    cudaGetSymbolAddress((void**)&p_vmean, g_vmean);
    cudaGetSymbolAddress((void**)&p_tk, g_topk);

    // top-k indices of C (12 * 1536 rows, one warp each)
    topk_fast<<<(12 * NN) / 8, 256>>>(C, p_tk);

    // 1) qkv = H @ in_proj_w^T + b
    gemm_qkv<<<dim3(768/BN, ROWS_TOT/BM), 256>>>(H, ipw, ipb, p_qkv, DD);

    // 2) tiny 4x4 attention over views
    view_attn<<<(NN*NHEADS)/8, 256>>>(p_qkv, p_o);

    // 3) aligned = a*(o @ out_w^T + b) + (1-a)*H
    gemm_out<<<dim3(DD/BN, ROWS_TOT/BM), 256>>>(p_o, ow, ob, p_aligned, H, alphas, DD);

    // 4) fused per-view Qn(fp32)/Kn(fp16)/Vn(fp16), one 288-block launch
    gemm_qkvn<<<dim3(DD/BN, NN/BM, 12), 256>>>(p_aligned, WQ, WK, WV,
                                               p_Qn, p_Kh, p_Vh, DD);

    // 5) mean of Vn over tokens (p==q uniform softmax term)
    vmean_partial<<<dim3(VV, 8), 256>>>(p_Vh, p_part);
    vmean_final<<<VV, 256>>>(p_part, p_vmean);

    // 6) sparse neighbor attention + final relu/fuse
    nbr_out<<<ROWS_TOT, 256>>>(p_Qn, p_Kh, p_Vh, p_vmean, p_tk,
                               p_aligned, H, aal, bet, out);
}

// round 3
// speedup vs baseline: 3.1087x; 1.2772x over previous
#include <cuda_runtime.h>
#include <cuda_fp16.h>
#include <mma.h>
#include <math.h>

using namespace nvcuda;

#define VV 4
#define NN 1536
#define DD 256
#define TOPK 32
#define NHEADS 4
#define HD 64
#define ROWS_TOT (VV*NN)   // 6144
#define CAP 256

// ---------------- scratch (device globals; no allocation allowed) ----------
__device__ float  g_qkv[VV*NN*3*DD];
__device__ float  g_o[VV*NN*DD];
__device__ float  g_aligned[VV*NN*DD];
__device__ float  g_Qn[VV*NN*DD];
__device__ __half g_Kh[VV*NN*DD];
__device__ __half g_Vh[VV*NN*DD];
__device__ float  g_part[VV*8*DD];
__device__ float  g_vmean[VV*DD];
__device__ int    g_topk[VV*VV*NN*TOPK];

// ---------------- tensor-core GEMM: C[m,n] = sum_k A[m,k]*B[n,k] -----------
// fp32 inputs converted to fp16 on smem fill; fp32 accumulate (HMMA).
// 128x128 tile, BK=32, 8 warps = 2(M) x 4(N), warp tile 64x32.
// MODE 0: out = gemm + bias                 (ld = Ncols)
// MODE 1: out = a*(gemm + bias) + (1-a)*Hx  (ld = DD)
// MODE 2: z=blockIdx.z -> which=z>>2 (0:Q f32, 1:K f16, 2:V f16), v=z&3
#define BKW 32
#define LDA 40          // halves, %8==0 for wmma
#define LDS_ 20         // floats, %4==0 for wmma accumulator store

template<int MODE>
__global__ __launch_bounds__(256, 2)
void hgemm(const float* __restrict__ A0, const float* __restrict__ W0,
           const float* __restrict__ W1, const float* __restrict__ W2,
           const float* __restrict__ bias,
           const float* __restrict__ Hx, const float* __restrict__ alphas,
           float* __restrict__ outF, __half* __restrict__ outK,
           __half* __restrict__ outV, int Ncols)
{
    const int K = DD;
    const float* A = A0;
    const float* B = W0;
    long obase = 0;
    int which = 0;
    if (MODE == 2) {
        int z = blockIdx.z; which = z >> 2; int v = z & 3;
        A = A0 + (long)v * NN * DD;
        B = (which == 0 ? W0 : which == 1 ? W1 : W2) + (long)v * DD * DD;
        obase = (long)v * NN * DD;
    }

    __shared__ __align__(16) __half As[128 * LDA];
    __shared__ __align__(16) __half Bs[128 * LDA];
    __shared__ float stage[8][16 * LDS_];

    const int tid = threadIdx.x;
    const int w = tid >> 5, lane = tid & 31;
    const int wm = w >> 2, wn = w & 3;
    const int m0 = blockIdx.y * 128, n0 = blockIdx.x * 128;

    wmma::fragment<wmma::accumulator, 16, 16, 16, float> cf[4][2];
#pragma unroll
    for (int i = 0; i < 4; i++)
#pragma unroll
        for (int j = 0; j < 2; j++) wmma::fill_fragment(cf[i][j], 0.f);

    for (int k0 = 0; k0 < K; k0 += BKW) {
#pragma unroll
        for (int p = 0; p < 4; p++) {
            int idx = tid + p * 256;         // 0..1023
            int row = idx >> 3;              // 128 rows
            int c4  = idx & 7;               // 8 float4 per row
            float4 av = *reinterpret_cast<const float4*>(
                &A[(long)(m0 + row) * K + k0 + c4 * 4]);
            __half2* da = reinterpret_cast<__half2*>(&As[row * LDA + c4 * 4]);
            da[0] = __floats2half2_rn(av.x, av.y);
            da[1] = __floats2half2_rn(av.z, av.w);
            float4 bv = *reinterpret_cast<const float4*>(
                &B[(long)(n0 + row) * K + k0 + c4 * 4]);
            __half2* db = reinterpret_cast<__half2*>(&Bs[row * LDA + c4 * 4]);
            db[0] = __floats2half2_rn(bv.x, bv.y);
            db[1] = __floats2half2_rn(bv.z, bv.w);
        }
        __syncthreads();

#pragma unroll
        for (int kk = 0; kk < BKW; kk += 16) {
            wmma::fragment<wmma::matrix_a, 16, 16, 16, __half, wmma::row_major> af[4];
#pragma unroll
            for (int i = 0; i < 4; i++)
                wmma::load_matrix_sync(af[i], &As[(wm*64 + i*16) * LDA + kk], LDA);
            wmma::fragment<wmma::matrix_b, 16, 16, 16, __half, wmma::col_major> bf[2];
#pragma unroll
            for (int j = 0; j < 2; j++)
                wmma::load_matrix_sync(bf[j], &Bs[(wn*32 + j*16) * LDA + kk], LDA);
#pragma unroll
            for (int i = 0; i < 4; i++)
#pragma unroll
                for (int j = 0; j < 2; j++)
                    wmma::mma_sync(cf[i][j], af[i], bf[j], cf[i][j]);
        }
        __syncthreads();
    }

    // epilogue: stage each 16x16 fragment through smem (layout-agnostic)
    const int erow = lane >> 1, ecol0 = (lane & 1) * 8;
#pragma unroll
    for (int i = 0; i < 4; i++)
#pragma unroll
        for (int j = 0; j < 2; j++) {
            wmma::store_matrix_sync(&stage[w][0], cf[i][j], LDS_, wmma::mem_row_major);
            __syncwarp();
            int r = m0 + wm*64 + i*16 + erow;
            int c = n0 + wn*32 + j*16 + ecol0;
            const float* sp = &stage[w][erow * LDS_ + ecol0];
            if (MODE == 0) {
                long off = (long)r * Ncols + c;
#pragma unroll
                for (int e = 0; e < 8; e++) outF[off + e] = sp[e] + bias[c + e];
            } else if (MODE == 1) {
                float a = alphas[r / NN];
                long off = (long)r * DD + c;
#pragma unroll
                for (int e = 0; e < 8; e++)
                    outF[off + e] = a * (sp[e] + bias[c + e]) + (1.f - a) * Hx[off + e];
            } else {
                long off = obase + (long)r * DD + c;
                if (which == 0) {
#pragma unroll
                    for (int e = 0; e < 8; e++) outF[off + e] = sp[e];
                } else if (which == 1) {
#pragma unroll
                    for (int e = 0; e < 8; e++) outK[off + e] = __float2half_rn(sp[e]);
                } else {
#pragma unroll
                    for (int e = 0; e < 8; e++) outV[off + e] = __float2half_rn(sp[e]);
                }
            }
            __syncwarp();
        }
}

// ---------------- tiny attention over views: one warp per (n,h) ------------
__global__ __launch_bounds__(256)
void view_attn(const float* __restrict__ qkv, float* __restrict__ o)
{
    int gw = blockIdx.x * 8 + (threadIdx.x >> 5);
    if (gw >= NN * NHEADS) return;
    int lane = threadIdx.x & 31;
    int n = gw >> 2;
    int h = gw & 3;

    float qf[VV][2], kf[VV][2], vf[VV][2];
#pragma unroll
    for (int l = 0; l < VV; l++) {
        long base = ((long)(l * NN + n)) * (3 * DD) + h * HD;
        qf[l][0] = qkv[base + lane];          qf[l][1] = qkv[base + lane + 32];
        kf[l][0] = qkv[base + DD + lane];     kf[l][1] = qkv[base + DD + lane + 32];
        vf[l][0] = qkv[base + 2*DD + lane];   vf[l][1] = qkv[base + 2*DD + lane + 32];
    }

    float s[VV][VV];
#pragma unroll
    for (int l = 0; l < VV; l++)
#pragma unroll
        for (int m = 0; m < VV; m++) {
            float p = qf[l][0]*kf[m][0] + qf[l][1]*kf[m][1];
#pragma unroll
            for (int off = 16; off; off >>= 1)
                p += __shfl_xor_sync(0xFFFFFFFFu, p, off);
            s[l][m] = p * 0.125f;
        }

#pragma unroll
    for (int l = 0; l < VV; l++) {
        float mx = fmaxf(fmaxf(s[l][0], s[l][1]), fmaxf(s[l][2], s[l][3]));
        float e0 = __expf(s[l][0]-mx), e1 = __expf(s[l][1]-mx),
              e2 = __expf(s[l][2]-mx), e3 = __expf(s[l][3]-mx);
        float inv = 1.f / (e0+e1+e2+e3);
        float o0 = (e0*vf[0][0] + e1*vf[1][0] + e2*vf[2][0] + e3*vf[3][0]) * inv;
        float o1 = (e0*vf[0][1] + e1*vf[1][1] + e2*vf[2][1] + e3*vf[3][1]) * inv;
        long base = ((long)(l * NN + n)) * DD + h * HD;
        o[base + lane]      = o0;
        o[base + lane + 32] = o1;
    }
}

// ---------------- fast top-32 per off-diagonal (v,q,n) row of C -------------
__global__ __launch_bounds__(256)
void topk_fast(const float* __restrict__ C, int* __restrict__ outIdx)
{
    __shared__ unsigned long long buf[8][CAP];
    const unsigned FULL = 0xFFFFFFFFu;
    int wid = threadIdx.x >> 5, lane = threadIdx.x & 31;
    int gw = blockIdx.x * 8 + wid;
    int pair = gw / NN, n = gw - pair * NN;
    int v = pair / 3, r3 = pair - v * 3;
    int q = r3 + (r3 >= v ? 1 : 0);

    const float* row = C + ((long)(v*4 + q) * NN + n) * (long)NN;
    int* outp = outIdx + ((long)(v*4 + q) * NN + n) * TOPK;
    unsigned long long* wbuf = buf[wid];

    int cnt = 0;
    float thr = 0.95f;
#pragma unroll 1
    for (int att = 0; att < 2; att++) {
        cnt = 0;
#pragma unroll 1
        for (int i = lane; i < NN; i += 32) {
            float x = row[i];
            bool p = x > thr;
            unsigned m = __ballot_sync(FULL, p);
            if (p) {
                int pos = cnt + __popc(m & ((1u << lane) - 1u));
                if (pos < CAP)
                    wbuf[pos] = (((unsigned long long)__float_as_uint(x)) << 32)
                              | (unsigned)(0xFFFFFFFFu - i);
            }
            cnt += __popc(m);
        }
        if (cnt >= TOPK && cnt <= CAP) break;
        thr = 0.90f;
    }

    if (cnt < TOPK || cnt > CAP) {
        unsigned long long prev = 0xFFFFFFFFFFFFFFFFull;
        for (int j = 0; j < TOPK; j++) {
            unsigned long long best = 0;
            for (int i = lane; i < NN; i += 32) {
                unsigned b = __float_as_uint(row[i]);
                unsigned key32 = (b & 0x80000000u) ? ~b : (b | 0x80000000u);
                unsigned long long k =
                    (((unsigned long long)key32) << 32) | (unsigned)(0xFFFFFFFFu - i);
                if (k < prev && k > best) best = k;
            }
#pragma unroll
            for (int off = 16; off; off >>= 1) {
                unsigned long long o = __shfl_xor_sync(FULL, best, off);
                if (o > best) best = o;
            }
            if (lane == 0) outp[j] = (int)(0xFFFFFFFFu - (unsigned)best);
            prev = best;
        }
        return;
    }

    const int SL = CAP / 32;
    unsigned long long c[SL];
#pragma unroll
    for (int k = 0; k < SL; k++) {
        int j = lane + 32 * k;
        c[k] = (j < cnt) ? wbuf[j] : 0ull;
    }
    unsigned long long lmax = 0; int lslot = 0;
#pragma unroll
    for (int k = 0; k < SL; k++) if (c[k] > lmax) { lmax = c[k]; lslot = k; }

#pragma unroll 1
    for (int j = 0; j < TOPK; j++) {
        unsigned long long best = lmax;
#pragma unroll
        for (int off = 16; off; off >>= 1) {
            unsigned long long o = __shfl_xor_sync(FULL, best, off);
            if (o > best) best = o;
        }
        if (lmax == best && best != 0ull) {
            outp[j] = (int)(0xFFFFFFFFu - (unsigned)best);
            c[lslot] = 0ull;
            lmax = 0; lslot = 0;
#pragma unroll
            for (int k = 0; k < SL; k++) if (c[k] > lmax) { lmax = c[k]; lslot = k; }
        }
    }
}

// ---------------- Vn mean over tokens (p==q uniform-softmax term) ----------
__global__ void vmean_partial(const __half* __restrict__ Vh, float* __restrict__ part)
{
    int v = blockIdx.x, chunk = blockIdx.y, t = threadIdx.x;
    float s = 0.f;
    int nbeg = chunk * (NN/8), nend = nbeg + (NN/8);
    for (int n = nbeg; n < nend; n++)
        s += __half2float(Vh[((long)v * NN + n) * DD + t]);
    part[(v*8 + chunk) * DD + t] = s;
}
__global__ void vmean_final(const float* __restrict__ part, float* __restrict__ vmean)
{
    int v = blockIdx.x, t = threadIdx.x;
    float s = 0.f;
#pragma unroll
    for (int c = 0; c < 8; c++) s += part[(v*8 + c) * DD + t];
    vmean[v * DD + t] = s * (1.0f / NN);
}

// ---------------- sparse neighbor attention + final fuse -------------------
__global__ __launch_bounds__(256)
void nbr_out(const float* __restrict__ Qn, const __half* __restrict__ Kh,
             const __half* __restrict__ Vh, const float* __restrict__ vmean,
             const int* __restrict__ topk, const float* __restrict__ aligned,
             const float* __restrict__ Hin,
             const float* __restrict__ alpha_align, const float* __restrict__ beta,
             float* __restrict__ out)
{
    int pn = blockIdx.x;
    int p = pn / NN, n = pn % NN;
    int t = threadIdx.x, lane = t & 31, wid = t >> 5;

    __shared__ float Qrow[DD];
    __shared__ float sdots[TOPK];
    __shared__ int   sidx[TOPK];

    long rowOff = (long)pn * DD;
    Qrow[t] = Qn[rowOff + t];
    float acc = vmean[p * DD + t];
    __syncthreads();

    for (int q = 0; q < VV; q++) {
        if (q == p) continue;
        if (t < TOPK)
            sidx[t] = topk[(((long)(p*VV + q)) * NN + n) * TOPK + t];
        __syncthreads();

        for (int j = wid; j < TOPK; j += 8) {
            const __half* krow = Kh + ((long)q * NN + sidx[j]) * DD;
            uint4 kv = *reinterpret_cast<const uint4*>(krow + lane * 8);
            float2 k0 = __half22float2(*reinterpret_cast<__half2*>(&kv.x));
            float2 k1 = __half22float2(*reinterpret_cast<__half2*>(&kv.y));
            float2 k2 = __half22float2(*reinterpret_cast<__half2*>(&kv.z));
            float2 k3 = __half22float2(*reinterpret_cast<__half2*>(&kv.w));
            float4 qa = *reinterpret_cast<const float4*>(&Qrow[lane*8]);
            float4 qb = *reinterpret_cast<const float4*>(&Qrow[lane*8+4]);
            float psum = qa.x*k0.x + qa.y*k0.y + qa.z*k1.x + qa.w*k1.y
                       + qb.x*k2.x + qb.y*k2.y + qb.z*k3.x + qb.w*k3.y;
#pragma unroll
            for (int off = 16; off; off >>= 1)
                psum += __shfl_xor_sync(0xFFFFFFFFu, psum, off);
            if (lane == 0) sdots[j] = psum * 0.0625f;
        }
        __syncthreads();

        if (wid == 0) {
            float x = sdots[lane];
            float mx = x;
#pragma unroll
            for (int off = 16; off; off >>= 1)
                mx = fmaxf(mx, __shfl_xor_sync(0xFFFFFFFFu, mx, off));
            float e = __expf(x - mx);
            float sm = e;
#pragma unroll
            for (int off = 16; off; off >>= 1)
                sm += __shfl_xor_sync(0xFFFFFFFFu, sm, off);
            sdots[lane] = e / sm;
        }
        __syncthreads();

#pragma unroll 8
        for (int j = 0; j < TOPK; j++)
            acc = fmaf(sdots[j],
                       __half2float(Vh[((long)q * NN + sidx[j]) * DD + t]), acc);
        __syncthreads();
    }

    float aa = 1.f / (1.f + __expf(-alpha_align[0]));
    float bb = 1.f / (1.f + __expf(-beta[0]));
    float al = aligned[rowOff + t];
    float f  = fmaxf(aa * al + (1.f - aa) * acc, 0.f);
    out[rowOff + t] = bb * Hin[rowOff + t] + (1.f - bb) * f;
}

// ---------------- launch ----------------------------------------------------
extern "C" void kernel_launch(void* const* d_in, const int* in_sizes, int n_in,
                              void* d_out, int out_size)
{
    const float* H      = (const float*)d_in[0];
    const float* C      = (const float*)d_in[1];
    const float* WQ     = (const float*)d_in[2];
    const float* WK     = (const float*)d_in[3];
    const float* WV     = (const float*)d_in[4];
    const float* ipw    = (const float*)d_in[5];
    const float* ipb    = (const float*)d_in[6];
    const float* ow     = (const float*)d_in[7];
    const float* ob     = (const float*)d_in[8];
    const float* alphas = (const float*)d_in[9];
    const float* aal    = (const float*)d_in[10];
    const float* bet    = (const float*)d_in[11];
    float* out = (float*)d_out;

    float *p_qkv, *p_o, *p_aligned, *p_Qn, *p_part, *p_vmean;
    __half *p_Kh, *p_Vh;
    int* p_tk;
    cudaGetSymbolAddress((void**)&p_qkv, g_qkv);
    cudaGetSymbolAddress((void**)&p_o, g_o);
    cudaGetSymbolAddress((void**)&p_aligned, g_aligned);
    cudaGetSymbolAddress((void**)&p_Qn, g_Qn);
    cudaGetSymbolAddress((void**)&p_Kh, g_Kh);
    cudaGetSymbolAddress((void**)&p_Vh, g_Vh);
    cudaGetSymbolAddress((void**)&p_part, g_part);
    cudaGetSymbolAddress((void**)&p_vmean, g_vmean);
    cudaGetSymbolAddress((void**)&p_tk, g_topk);

    // top-k indices of C (12 * 1536 rows, one warp each)
    topk_fast<<<(12 * NN) / 8, 256>>>(C, p_tk);

    // 1) qkv = H @ in_proj_w^T + b   (tensor cores)
    hgemm<0><<<dim3(768/128, ROWS_TOT/128), 256>>>(
        H, ipw, nullptr, nullptr, ipb, nullptr, nullptr,
        p_qkv, nullptr, nullptr, 3*DD);

    // 2) tiny 4x4 attention over views
    view_attn<<<(NN*NHEADS)/8, 256>>>(p_qkv, p_o);

    // 3) aligned = a*(o @ out_w^T + b) + (1-a)*H
    hgemm<1><<<dim3(DD/128, ROWS_TOT/128), 256>>>(
        p_o, ow, nullptr, nullptr, ob, H, alphas,
        p_aligned, nullptr, nullptr, DD);

    // 4) fused per-view Qn(f32)/Kn(f16)/Vn(f16)
    hgemm<2><<<dim3(DD/128, NN/128, 12), 256>>>(
        p_aligned, WQ, WK, WV, nullptr, nullptr, nullptr,
        p_Qn, p_Kh, p_Vh, DD);

    // 5) mean of Vn over tokens
    vmean_partial<<<dim3(VV, 8), 256>>>(p_Vh, p_part);
    vmean_final<<<VV, 256>>>(p_part, p_vmean);

    // 6) sparse neighbor attention + final relu/fuse
    nbr_out<<<ROWS_TOT, 256>>>(p_Qn, p_Kh, p_Vh, p_vmean, p_tk,
                               p_aligned, H, aal, bet, out);
}

// round 4
// speedup vs baseline: 3.1687x; 1.0193x over previous
#include <cuda_runtime.h>
#include <cuda_fp16.h>
#include <mma.h>
#include <math.h>

using namespace nvcuda;

#define VV 4
#define NN 1536
#define DD 256
#define TOPK 32
#define NHEADS 4
#define HD 64
#define ROWS_TOT (VV*NN)   // 6144
#define CAP 256

// ---------------- scratch (device globals; no allocation allowed) ----------
__device__ __half g_Hh[VV*NN*DD];          // H in fp16
__device__ __half g_ipwh[3*DD*DD];
__device__ __half g_owh[DD*DD];
__device__ __half g_WQh[VV*DD*DD];
__device__ __half g_WKh[VV*DD*DD];
__device__ __half g_WVh[VV*DD*DD];
__device__ float  g_qkv[VV*NN*3*DD];
__device__ __half g_oh[VV*NN*DD];
__device__ float  g_aligned[VV*NN*DD];
__device__ __half g_alignedh[VV*NN*DD];
__device__ float  g_Qn[VV*NN*DD];
__device__ __half g_Kh[VV*NN*DD];
__device__ __half g_Vh[VV*NN*DD];
__device__ float  g_part[VV*8*DD];
__device__ float  g_vmean[VV*DD];
__device__ int    g_topk[VV*VV*NN*TOPK];

// ---------------- fp32 -> fp16 convert (n multiple of 8) -------------------
__global__ void f2h(const float* __restrict__ in, __half* __restrict__ out, int n)
{
    int i = (blockIdx.x * 256 + threadIdx.x) * 8;
    if (i >= n) return;
    float4 a = *reinterpret_cast<const float4*>(in + i);
    float4 b = *reinterpret_cast<const float4*>(in + i + 4);
    __half2 h[4] = { __floats2half2_rn(a.x, a.y), __floats2half2_rn(a.z, a.w),
                     __floats2half2_rn(b.x, b.y), __floats2half2_rn(b.z, b.w) };
    *reinterpret_cast<uint4*>(out + i) = *reinterpret_cast<uint4*>(h);
}

// ---------------- cp.async helpers -----------------------------------------
__device__ __forceinline__ void cp16(void* smem, const void* gmem)
{
    unsigned s = (unsigned)__cvta_generic_to_shared(smem);
    asm volatile("cp.async.cg.shared.global [%0], [%1], 16;\n" :: "r"(s), "l"(gmem));
}
__device__ __forceinline__ void cp_commit()
{ asm volatile("cp.async.commit_group;\n"); }
template<int N> __device__ __forceinline__ void cp_wait()
{ asm volatile("cp.async.wait_group %0;\n" :: "n"(N)); }

// ---------------- tensor-core GEMM: C[m,n] = sum_k A[m,k]*B[n,k] -----------
// fp16 inputs, fp32 accumulate. Tile 64(M)x128(N), BK=32, double-buffered
// cp.async. 8 warps = 2(M) x 4(N); warp tile 32x32 = 2x2 wmma frags. K=256.
// MODE 0: outF = gemm + bias                        (ld = Ncols)
// MODE 1: v = a*(gemm+bias)+(1-a)*Hx -> outF(f32) + outH(f16)
// MODE 2: z -> which=z>>2 (0:Qn f32, 1:Kh, 2:Vh), v=z&3
#define LDA 40
#define LDS_ 20
#define KSTEPS (DD/32)

template<int MODE>
__global__ __launch_bounds__(256, 2)
void hgemm(const __half* __restrict__ A0, const __half* __restrict__ W0,
           const __half* __restrict__ W1, const __half* __restrict__ W2,
           const float* __restrict__ bias,
           const float* __restrict__ Hx, const float* __restrict__ alphas,
           float* __restrict__ outF, __half* __restrict__ outH,
           __half* __restrict__ outK, __half* __restrict__ outV, int Ncols)
{
    const int K = DD;
    const __half* A = A0;
    const __half* B = W0;
    long obase = 0;
    int which = 0;
    if (MODE == 2) {
        int z = blockIdx.z; which = z >> 2; int v = z & 3;
        A = A0 + (long)v * NN * DD;
        B = (which == 0 ? W0 : which == 1 ? W1 : W2) + (long)v * DD * DD;
        obase = (long)v * NN * DD;
    }

    __shared__ __align__(16) __half As[2][64 * LDA];
    __shared__ __align__(16) __half Bs[2][128 * LDA];
    __shared__ float stage[8][16 * LDS_];

    const int tid = threadIdx.x;
    const int w = tid >> 5, lane = tid & 31;
    const int wm = w >> 2, wn = w & 3;
    const int m0 = blockIdx.y * 64, n0 = blockIdx.x * 128;

    const int rowL = tid >> 2;       // 0..63
    const int ca   = tid & 3;        // chunk (8 halves)

    wmma::fragment<wmma::accumulator, 16, 16, 16, float> cf[2][2];
#pragma unroll
    for (int i = 0; i < 2; i++)
#pragma unroll
        for (int j = 0; j < 2; j++) wmma::fill_fragment(cf[i][j], 0.f);

    // prefetch stage 0
    {
        int k0 = 0;
        cp16(&As[0][rowL * LDA + ca * 8], &A[(long)(m0 + rowL) * K + k0 + ca * 8]);
        cp16(&Bs[0][rowL * LDA + ca * 8], &B[(long)(n0 + rowL) * K + k0 + ca * 8]);
        cp16(&Bs[0][(rowL + 64) * LDA + ca * 8],
             &B[(long)(n0 + rowL + 64) * K + k0 + ca * 8]);
        cp_commit();
    }

    for (int kt = 0; kt < KSTEPS; kt++) {
        if (kt + 1 < KSTEPS) {
            int k0 = (kt + 1) * 32, s = (kt + 1) & 1;
            cp16(&As[s][rowL * LDA + ca * 8], &A[(long)(m0 + rowL) * K + k0 + ca * 8]);
            cp16(&Bs[s][rowL * LDA + ca * 8], &B[(long)(n0 + rowL) * K + k0 + ca * 8]);
            cp16(&Bs[s][(rowL + 64) * LDA + ca * 8],
                 &B[(long)(n0 + rowL + 64) * K + k0 + ca * 8]);
            cp_commit();
            cp_wait<1>();
        } else {
            cp_wait<0>();
        }
        __syncthreads();

        const __half* Ab = As[kt & 1];
        const __half* Bb = Bs[kt & 1];
#pragma unroll
        for (int kk = 0; kk < 32; kk += 16) {
            wmma::fragment<wmma::matrix_a, 16, 16, 16, __half, wmma::row_major> af[2];
            wmma::fragment<wmma::matrix_b, 16, 16, 16, __half, wmma::col_major> bf[2];
#pragma unroll
            for (int i = 0; i < 2; i++)
                wmma::load_matrix_sync(af[i], &Ab[(wm*32 + i*16) * LDA + kk], LDA);
#pragma unroll
            for (int j = 0; j < 2; j++)
                wmma::load_matrix_sync(bf[j], &Bb[(wn*32 + j*16) * LDA + kk], LDA);
#pragma unroll
            for (int i = 0; i < 2; i++)
#pragma unroll
                for (int j = 0; j < 2; j++)
                    wmma::mma_sync(cf[i][j], af[i], bf[j], cf[i][j]);
        }
        __syncthreads();
    }

    // epilogue: stage each 16x16 fragment through smem
    const int erow = lane >> 1, ecol0 = (lane & 1) * 8;
#pragma unroll
    for (int i = 0; i < 2; i++)
#pragma unroll
        for (int j = 0; j < 2; j++) {
            wmma::store_matrix_sync(&stage[w][0], cf[i][j], LDS_, wmma::mem_row_major);
            __syncwarp();
            int r = m0 + wm*32 + i*16 + erow;
            int c = n0 + wn*32 + j*16 + ecol0;
            const float* sp = &stage[w][erow * LDS_ + ecol0];
            if (MODE == 0) {
                long off = (long)r * Ncols + c;
#pragma unroll
                for (int e = 0; e < 8; e++) outF[off + e] = sp[e] + bias[c + e];
            } else if (MODE == 1) {
                float a = alphas[r / NN];
                long off = (long)r * DD + c;
#pragma unroll
                for (int e = 0; e < 8; e++) {
                    float v = a * (sp[e] + bias[c + e]) + (1.f - a) * Hx[off + e];
                    outF[off + e] = v;
                    outH[off + e] = __float2half_rn(v);
                }
            } else {
                long off = obase + (long)r * DD + c;
                if (which == 0) {
#pragma unroll
                    for (int e = 0; e < 8; e++) outF[off + e] = sp[e];
                } else if (which == 1) {
#pragma unroll
                    for (int e = 0; e < 8; e++) outK[off + e] = __float2half_rn(sp[e]);
                } else {
#pragma unroll
                    for (int e = 0; e < 8; e++) outV[off + e] = __float2half_rn(sp[e]);
                }
            }
            __syncwarp();
        }
}

// ---------------- tiny attention over views: one warp per (n,h) ------------
__global__ __launch_bounds__(256)
void view_attn(const float* __restrict__ qkv, __half* __restrict__ o)
{
    int gw = blockIdx.x * 8 + (threadIdx.x >> 5);
    if (gw >= NN * NHEADS) return;
    int lane = threadIdx.x & 31;
    int n = gw >> 2;
    int h = gw & 3;

    float qf[VV][2], kf[VV][2], vf[VV][2];
#pragma unroll
    for (int l = 0; l < VV; l++) {
        long base = ((long)(l * NN + n)) * (3 * DD) + h * HD;
        qf[l][0] = qkv[base + lane];          qf[l][1] = qkv[base + lane + 32];
        kf[l][0] = qkv[base + DD + lane];     kf[l][1] = qkv[base + DD + lane + 32];
        vf[l][0] = qkv[base + 2*DD + lane];   vf[l][1] = qkv[base + 2*DD + lane + 32];
    }

    float s[VV][VV];
#pragma unroll
    for (int l = 0; l < VV; l++)
#pragma unroll
        for (int m = 0; m < VV; m++) {
            float p = qf[l][0]*kf[m][0] + qf[l][1]*kf[m][1];
#pragma unroll
            for (int off = 16; off; off >>= 1)
                p += __shfl_xor_sync(0xFFFFFFFFu, p, off);
            s[l][m] = p * 0.125f;
        }

#pragma unroll
    for (int l = 0; l < VV; l++) {
        float mx = fmaxf(fmaxf(s[l][0], s[l][1]), fmaxf(s[l][2], s[l][3]));
        float e0 = __expf(s[l][0]-mx), e1 = __expf(s[l][1]-mx),
              e2 = __expf(s[l][2]-mx), e3 = __expf(s[l][3]-mx);
        float inv = 1.f / (e0+e1+e2+e3);
        float o0 = (e0*vf[0][0] + e1*vf[1][0] + e2*vf[2][0] + e3*vf[3][0]) * inv;
        float o1 = (e0*vf[0][1] + e1*vf[1][1] + e2*vf[2][1] + e3*vf[3][1]) * inv;
        long base = ((long)(l * NN + n)) * DD + h * HD;
        o[base + lane]      = __float2half_rn(o0);
        o[base + lane + 32] = __float2half_rn(o1);
    }
}

// ---------------- fast top-32 per off-diagonal (v,q,n) row of C -------------
__global__ __launch_bounds__(256)
void topk_fast(const float* __restrict__ C, int* __restrict__ outIdx)
{
    __shared__ unsigned long long buf[8][CAP];
    const unsigned FULL = 0xFFFFFFFFu;
    int wid = threadIdx.x >> 5, lane = threadIdx.x & 31;
    int gw = blockIdx.x * 8 + wid;
    int pair = gw / NN, n = gw - pair * NN;
    int v = pair / 3, r3 = pair - v * 3;
    int q = r3 + (r3 >= v ? 1 : 0);

    const float* row = C + ((long)(v*4 + q) * NN + n) * (long)NN;
    int* outp = outIdx + ((long)(v*4 + q) * NN + n) * TOPK;
    unsigned long long* wbuf = buf[wid];

    int cnt = 0;
    float thr = 0.95f;
#pragma unroll 1
    for (int att = 0; att < 2; att++) {
        cnt = 0;
#pragma unroll 1
        for (int i = lane; i < NN; i += 32) {
            float x = row[i];
            bool p = x > thr;
            unsigned m = __ballot_sync(FULL, p);
            if (p) {
                int pos = cnt + __popc(m & ((1u << lane) - 1u));
                if (pos < CAP)
                    wbuf[pos] = (((unsigned long long)__float_as_uint(x)) << 32)
                              | (unsigned)(0xFFFFFFFFu - i);
            }
            cnt += __popc(m);
        }
        if (cnt >= TOPK && cnt <= CAP) break;
        thr = 0.90f;
    }

    if (cnt < TOPK || cnt > CAP) {
        unsigned long long prev = 0xFFFFFFFFFFFFFFFFull;
        for (int j = 0; j < TOPK; j++) {
            unsigned long long best = 0;
            for (int i = lane; i < NN; i += 32) {
                unsigned b = __float_as_uint(row[i]);
                unsigned key32 = (b & 0x80000000u) ? ~b : (b | 0x80000000u);
                unsigned long long k =
                    (((unsigned long long)key32) << 32) | (unsigned)(0xFFFFFFFFu - i);
                if (k < prev && k > best) best = k;
            }
#pragma unroll
            for (int off = 16; off; off >>= 1) {
                unsigned long long o = __shfl_xor_sync(FULL, best, off);
                if (o > best) best = o;
            }
            if (lane == 0) outp[j] = (int)(0xFFFFFFFFu - (unsigned)best);
            prev = best;
        }
        return;
    }

    const int SL = CAP / 32;
    unsigned long long c[SL];
#pragma unroll
    for (int k = 0; k < SL; k++) {
        int j = lane + 32 * k;
        c[k] = (j < cnt) ? wbuf[j] : 0ull;
    }
    unsigned long long lmax = 0; int lslot = 0;
#pragma unroll
    for (int k = 0; k < SL; k++) if (c[k] > lmax) { lmax = c[k]; lslot = k; }

#pragma unroll 1
    for (int j = 0; j < TOPK; j++) {
        unsigned long long best = lmax;
#pragma unroll
        for (int off = 16; off; off >>= 1) {
            unsigned long long o = __shfl_xor_sync(FULL, best, off);
            if (o > best) best = o;
        }
        if (lmax == best && best != 0ull) {
            outp[j] = (int)(0xFFFFFFFFu - (unsigned)best);
            c[lslot] = 0ull;
            lmax = 0; lslot = 0;
#pragma unroll
            for (int k = 0; k < SL; k++) if (c[k] > lmax) { lmax = c[k]; lslot = k; }
        }
    }
}

// ---------------- Vn mean over tokens (p==q uniform-softmax term) ----------
__global__ void vmean_partial(const __half* __restrict__ Vh, float* __restrict__ part)
{
    int v = blockIdx.x, chunk = blockIdx.y, t = threadIdx.x;
    float s = 0.f;
    int nbeg = chunk * (NN/8), nend = nbeg + (NN/8);
    for (int n = nbeg; n < nend; n++)
        s += __half2float(Vh[((long)v * NN + n) * DD + t]);
    part[(v*8 + chunk) * DD + t] = s;
}
__global__ void vmean_final(const float* __restrict__ part, float* __restrict__ vmean)
{
    int v = blockIdx.x, t = threadIdx.x;
    float s = 0.f;
#pragma unroll
    for (int c = 0; c < 8; c++) s += part[(v*8 + c) * DD + t];
    vmean[v * DD + t] = s * (1.0f / NN);
}

// ---------------- sparse neighbor attention + final fuse -------------------
// One block per (p,n). All 96 neighbor keys handled in one pass: 3 barriers.
__global__ __launch_bounds__(256)
void nbr_out(const float* __restrict__ Qn, const __half* __restrict__ Kh,
             const __half* __restrict__ Vh, const float* __restrict__ vmean,
             const int* __restrict__ topk, const float* __restrict__ aligned,
             const float* __restrict__ Hin,
             const float* __restrict__ alpha_align, const float* __restrict__ beta,
             float* __restrict__ out)
{
    int pn = blockIdx.x;
    int p = pn / NN, n = pn % NN;
    int t = threadIdx.x, lane = t & 31, wid = t >> 5;

    __shared__ float Qrow[DD];
    __shared__ float sdots[96];
    __shared__ int   srow[96];     // global K/V row = q*NN + idx

    long rowOff = (long)pn * DD;
    Qrow[t] = Qn[rowOff + t];
    if (t < 96) {
        int view = t >> 5;                       // 0..2
        int q = view + (view >= p ? 1 : 0);      // skip q == p
        int idx = topk[(((long)(p*VV + q)) * NN + n) * TOPK + (t & 31)];
        srow[t] = q * NN + idx;
    }
    float acc = vmean[p * DD + t];   // q==p: fully-masked softmax -> uniform mean
    __syncthreads();

    // 96 dot products, 12 per warp
#pragma unroll 2
    for (int j = wid; j < 96; j += 8) {
        const __half* krow = Kh + (long)srow[j] * DD;
        uint4 kv = *reinterpret_cast<const uint4*>(krow + lane * 8);
        float2 k0 = __half22float2(*reinterpret_cast<__half2*>(&kv.x));
        float2 k1 = __half22float2(*reinterpret_cast<__half2*>(&kv.y));
        float2 k2 = __half22float2(*reinterpret_cast<__half2*>(&kv.z));
        float2 k3 = __half22float2(*reinterpret_cast<__half2*>(&kv.w));
        float4 qa = *reinterpret_cast<const float4*>(&Qrow[lane*8]);
        float4 qb = *reinterpret_cast<const float4*>(&Qrow[lane*8+4]);
        float psum = qa.x*k0.x + qa.y*k0.y + qa.z*k1.x + qa.w*k1.y
                   + qb.x*k2.x + qb.y*k2.y + qb.z*k3.x + qb.w*k3.y;
#pragma unroll
        for (int off = 16; off; off >>= 1)
            psum += __shfl_xor_sync(0xFFFFFFFFu, psum, off);
        if (lane == 0) sdots[j] = psum * 0.0625f;
    }
    __syncthreads();

    // 3 softmaxes (one view per warp) in parallel
    if (wid < 3) {
        float x = sdots[wid*32 + lane];
        float mx = x;
#pragma unroll
        for (int off = 16; off; off >>= 1)
            mx = fmaxf(mx, __shfl_xor_sync(0xFFFFFFFFu, mx, off));
        float e = __expf(x - mx);
        float sm = e;
#pragma unroll
        for (int off = 16; off; off >>= 1)
            sm += __shfl_xor_sync(0xFFFFFFFFu, sm, off);
        sdots[wid*32 + lane] = e / sm;
    }
    __syncthreads();

    // weighted V accumulation: 96 steps, 2 partial accumulators
    float a1 = 0.f;
#pragma unroll 8
    for (int j = 0; j < 96; j += 2) {
        acc = fmaf(sdots[j],   __half2float(Vh[(long)srow[j]   * DD + t]), acc);
        a1  = fmaf(sdots[j+1], __half2float(Vh[(long)srow[j+1] * DD + t]), a1);
    }
    acc += a1;

    float aa = 1.f / (1.f + __expf(-alpha_align[0]));
    float bb = 1.f / (1.f + __expf(-beta[0]));
    float al = aligned[rowOff + t];
    float f  = fmaxf(aa * al + (1.f - aa) * acc, 0.f);
    out[rowOff + t] = bb * Hin[rowOff + t] + (1.f - bb) * f;
}

// ---------------- launch ----------------------------------------------------
extern "C" void kernel_launch(void* const* d_in, const int* in_sizes, int n_in,
                              void* d_out, int out_size)
{
    const float* H      = (const float*)d_in[0];
    const float* C      = (const float*)d_in[1];
    const float* WQ     = (const float*)d_in[2];
    const float* WK     = (const float*)d_in[3];
    const float* WV     = (const float*)d_in[4];
    const float* ipw    = (const float*)d_in[5];
    const float* ipb    = (const float*)d_in[6];
    const float* ow     = (const float*)d_in[7];
    const float* ob     = (const float*)d_in[8];
    const float* alphas = (const float*)d_in[9];
    const float* aal    = (const float*)d_in[10];
    const float* bet    = (const float*)d_in[11];
    float* out = (float*)d_out;

    __half *p_Hh, *p_ipwh, *p_owh, *p_WQh, *p_WKh, *p_WVh;
    __half *p_oh, *p_alignedh, *p_Kh, *p_Vh;
    float *p_qkv, *p_aligned, *p_Qn, *p_part, *p_vmean;
    int* p_tk;
    cudaGetSymbolAddress((void**)&p_Hh, g_Hh);
    cudaGetSymbolAddress((void**)&p_ipwh, g_ipwh);
    cudaGetSymbolAddress((void**)&p_owh, g_owh);
    cudaGetSymbolAddress((void**)&p_WQh, g_WQh);
    cudaGetSymbolAddress((void**)&p_WKh, g_WKh);
    cudaGetSymbolAddress((void**)&p_WVh, g_WVh);
    cudaGetSymbolAddress((void**)&p_qkv, g_qkv);
    cudaGetSymbolAddress((void**)&p_oh, g_oh);
    cudaGetSymbolAddress((void**)&p_aligned, g_aligned);
    cudaGetSymbolAddress((void**)&p_alignedh, g_alignedh);
    cudaGetSymbolAddress((void**)&p_Qn, g_Qn);
    cudaGetSymbolAddress((void**)&p_Kh, g_Kh);
    cudaGetSymbolAddress((void**)&p_Vh, g_Vh);
    cudaGetSymbolAddress((void**)&p_part, g_part);
    cudaGetSymbolAddress((void**)&p_vmean, g_vmean);
    cudaGetSymbolAddress((void**)&p_tk, g_topk);

    auto cgrid = [](int n){ return (n/8 + 255) / 256; };

    // fp16 conversions (inputs to GEMMs)
    f2h<<<cgrid(ROWS_TOT*DD), 256>>>(H, p_Hh, ROWS_TOT*DD);
    f2h<<<cgrid(3*DD*DD), 256>>>(ipw, p_ipwh, 3*DD*DD);
    f2h<<<cgrid(DD*DD), 256>>>(ow, p_owh, DD*DD);
    f2h<<<cgrid(VV*DD*DD), 256>>>(WQ, p_WQh, VV*DD*DD);
    f2h<<<cgrid(VV*DD*DD), 256>>>(WK, p_WKh, VV*DD*DD);
    f2h<<<cgrid(VV*DD*DD), 256>>>(WV, p_WVh, VV*DD*DD);

    // top-k indices of C
    topk_fast<<<(12 * NN) / 8, 256>>>(C, p_tk);

    // 1) qkv = H @ in_proj_w^T + b
    hgemm<0><<<dim3(768/128, ROWS_TOT/64), 256>>>(
        p_Hh, p_ipwh, nullptr, nullptr, ipb, nullptr, nullptr,
        p_qkv, nullptr, nullptr, nullptr, 3*DD);

    // 2) tiny 4x4 attention over views -> o (fp16)
    view_attn<<<(NN*NHEADS)/8, 256>>>(p_qkv, p_oh);

    // 3) aligned = a*(o @ out_w^T + b) + (1-a)*H   (f32 + f16 copies)
    hgemm<1><<<dim3(DD/128, ROWS_TOT/64), 256>>>(
        p_oh, p_owh, nullptr, nullptr, ob, H, alphas,
        p_aligned, p_alignedh, nullptr, nullptr, DD);

    // 4) fused per-view Qn(f32)/Kh/Vh
    hgemm<2><<<dim3(DD/128, NN/64, 12), 256>>>(
        p_alignedh, p_WQh, p_WKh, p_WVh, nullptr, nullptr, nullptr,
        p_Qn, nullptr, p_Kh, p_Vh, DD);

    // 5) mean of Vn over tokens
    vmean_partial<<<dim3(VV, 8), 256>>>(p_Vh, p_part);
    vmean_final<<<VV, 256>>>(p_part, p_vmean);

    // 6) sparse neighbor attention + final relu/fuse
    nbr_out<<<ROWS_TOT, 256>>>(p_Qn, p_Kh, p_Vh, p_vmean, p_tk,
                               p_aligned, H, aal, bet, out);
}

// round 5
// speedup vs baseline: 3.5442x; 1.1185x over previous
#include <cuda_runtime.h>
#include <cuda_fp16.h>
#include <mma.h>
#include <math.h>

using namespace nvcuda;

#define VV 4
#define NN 1536
#define DD 256
#define TOPK 32
#define NHEADS 4
#define HD 64
#define ROWS_TOT (VV*NN)   // 6144
#define CAP 256

// ---------------- scratch (device globals; no allocation allowed) ----------
__device__ __half g_Hh[VV*NN*DD];
__device__ __half g_ipwh[3*DD*DD];
__device__ __half g_owh[DD*DD];
__device__ __half g_WQh[VV*DD*DD];
__device__ __half g_WKh[VV*DD*DD];
__device__ __half g_WVh[VV*DD*DD];
__device__ __half g_qkvh[VV*NN*3*DD];
__device__ __half g_oh[VV*NN*DD];
__device__ float  g_aligned[VV*NN*DD];
__device__ __half g_alignedh[VV*NN*DD];
__device__ float  g_Qn[VV*NN*DD];
__device__ __half g_Kh[VV*NN*DD];
__device__ __half g_Vh[VV*NN*DD];
__device__ float  g_part[VV*8*DD];
__device__ float  g_vmean[VV*DD];
__device__ int    g_topk[VV*VV*NN*TOPK];

// ---------------- fp32 -> fp16 convert (n multiple of 8) -------------------
__global__ void f2h(const float* __restrict__ in, __half* __restrict__ out, int n)
{
    int i = (blockIdx.x * 256 + threadIdx.x) * 8;
    if (i >= n) return;
    float4 a = *reinterpret_cast<const float4*>(in + i);
    float4 b = *reinterpret_cast<const float4*>(in + i + 4);
    __half2 h[4] = { __floats2half2_rn(a.x, a.y), __floats2half2_rn(a.z, a.w),
                     __floats2half2_rn(b.x, b.y), __floats2half2_rn(b.z, b.w) };
    *reinterpret_cast<uint4*>(out + i) = *reinterpret_cast<uint4*>(h);
}

// ---------------- cp.async helpers -----------------------------------------
__device__ __forceinline__ void cp16(void* smem, const void* gmem)
{
    unsigned s = (unsigned)__cvta_generic_to_shared(smem);
    asm volatile("cp.async.cg.shared.global [%0], [%1], 16;\n" :: "r"(s), "l"(gmem));
}
__device__ __forceinline__ void cp_commit()
{ asm volatile("cp.async.commit_group;\n"); }
template<int N> __device__ __forceinline__ void cp_wait()
{ asm volatile("cp.async.wait_group %0;\n" :: "n"(N)); }

// ---------------- tensor-core GEMM: C[m,n] = sum_k A[m,k]*B[n,k] -----------
// fp16 in, fp32 accumulate. Tile 64(M)x128(N), BK=32, K=256 (8 steps).
// 4-stage cp.async pipeline, ONE barrier per step. 8 warps = 2(M)x4(N),
// warp tile 32x32. Dynamic smem 61440B; epilogue staged over pipeline bufs.
// MODE 0: outH = half(gemm + bias)                  (ld = Ncols)
// MODE 1: v = a*(gemm+bias)+(1-a)*Hx -> outF + outH
// MODE 2: z -> which=z>>2 (0:Qn f32, 1:Kh, 2:Vh), v=z&3
#define LDA 40
#define LDS_ 20
#define KSTEPS (DD/32)
#define STAGES 4
#define HG_SMEM (STAGES*(64+128)*LDA*2)

template<int MODE>
__global__ __launch_bounds__(256, 2)
void hgemm(const __half* __restrict__ A0, const __half* __restrict__ W0,
           const __half* __restrict__ W1, const __half* __restrict__ W2,
           const float* __restrict__ bias,
           const float* __restrict__ Hx, const float* __restrict__ alphas,
           float* __restrict__ outF, __half* __restrict__ outH,
           __half* __restrict__ outK, __half* __restrict__ outV, int Ncols)
{
    const int K = DD;
    const __half* A = A0;
    const __half* B = W0;
    long obase = 0;
    int which = 0;
    if (MODE == 2) {
        int z = blockIdx.z; which = z >> 2; int v = z & 3;
        A = A0 + (long)v * NN * DD;
        B = (which == 0 ? W0 : which == 1 ? W1 : W2) + (long)v * DD * DD;
        obase = (long)v * NN * DD;
    }

    extern __shared__ __align__(16) char gsm[];
    __half* As = reinterpret_cast<__half*>(gsm);                     // STAGES*64*LDA
    __half* Bs = As + STAGES * 64 * LDA;                             // STAGES*128*LDA
    float*  stage = reinterpret_cast<float*>(gsm);                   // reused post-loop

    const int tid = threadIdx.x;
    const int w = tid >> 5, lane = tid & 31;
    const int wm = w >> 2, wn = w & 3;
    const int m0 = blockIdx.y * 64, n0 = blockIdx.x * 128;
    const int rowL = tid >> 2;       // 0..63
    const int ca   = tid & 3;        // 8-half chunk

    wmma::fragment<wmma::accumulator, 16, 16, 16, float> cf[2][2];
#pragma unroll
    for (int i = 0; i < 2; i++)
#pragma unroll
        for (int j = 0; j < 2; j++) wmma::fill_fragment(cf[i][j], 0.f);

    auto issue = [&](int kt) {
        int s = kt & (STAGES - 1);
        int k0 = kt * 32;
        cp16(&As[(s*64 + rowL) * LDA + ca * 8],
             &A[(long)(m0 + rowL) * K + k0 + ca * 8]);
        cp16(&Bs[(s*128 + rowL) * LDA + ca * 8],
             &B[(long)(n0 + rowL) * K + k0 + ca * 8]);
        cp16(&Bs[(s*128 + rowL + 64) * LDA + ca * 8],
             &B[(long)(n0 + rowL + 64) * K + k0 + ca * 8]);
    };

    issue(0); cp_commit();
    issue(1); cp_commit();

    for (int kt = 0; kt < KSTEPS; kt++) {
        if (kt + 2 < KSTEPS) issue(kt + 2);
        cp_commit();
        cp_wait<2>();
        __syncthreads();

        const __half* Ab = &As[(kt & (STAGES-1)) * 64 * LDA];
        const __half* Bb = &Bs[(kt & (STAGES-1)) * 128 * LDA];
#pragma unroll
        for (int kk = 0; kk < 32; kk += 16) {
            wmma::fragment<wmma::matrix_a, 16, 16, 16, __half, wmma::row_major> af[2];
            wmma::fragment<wmma::matrix_b, 16, 16, 16, __half, wmma::col_major> bf[2];
#pragma unroll
            for (int i = 0; i < 2; i++)
                wmma::load_matrix_sync(af[i], &Ab[(wm*32 + i*16) * LDA + kk], LDA);
#pragma unroll
            for (int j = 0; j < 2; j++)
                wmma::load_matrix_sync(bf[j], &Bb[(wn*32 + j*16) * LDA + kk], LDA);
#pragma unroll
            for (int i = 0; i < 2; i++)
#pragma unroll
                for (int j = 0; j < 2; j++)
                    wmma::mma_sync(cf[i][j], af[i], bf[j], cf[i][j]);
        }
    }
    __syncthreads();   // all MMAs done before reusing smem for epilogue

    const int erow = lane >> 1, ecol0 = (lane & 1) * 8;
    float* wstage = &stage[w * 16 * LDS_];
#pragma unroll
    for (int i = 0; i < 2; i++)
#pragma unroll
        for (int j = 0; j < 2; j++) {
            wmma::store_matrix_sync(wstage, cf[i][j], LDS_, wmma::mem_row_major);
            __syncwarp();
            int r = m0 + wm*32 + i*16 + erow;
            int c = n0 + wn*32 + j*16 + ecol0;
            const float* sp = &wstage[erow * LDS_ + ecol0];
            if (MODE == 0) {
                long off = (long)r * Ncols + c;
#pragma unroll
                for (int e = 0; e < 8; e++)
                    outH[off + e] = __float2half_rn(sp[e] + bias[c + e]);
            } else if (MODE == 1) {
                float a = alphas[r / NN];
                long off = (long)r * DD + c;
#pragma unroll
                for (int e = 0; e < 8; e++) {
                    float v = a * (sp[e] + bias[c + e]) + (1.f - a) * Hx[off + e];
                    outF[off + e] = v;
                    outH[off + e] = __float2half_rn(v);
                }
            } else {
                long off = obase + (long)r * DD + c;
                if (which == 0) {
#pragma unroll
                    for (int e = 0; e < 8; e++) outF[off + e] = sp[e];
                } else if (which == 1) {
#pragma unroll
                    for (int e = 0; e < 8; e++) outK[off + e] = __float2half_rn(sp[e]);
                } else {
#pragma unroll
                    for (int e = 0; e < 8; e++) outV[off + e] = __float2half_rn(sp[e]);
                }
            }
            __syncwarp();
        }
}

// ---------------- tiny attention over views: one warp per (n,h) ------------
__global__ __launch_bounds__(256)
void view_attn(const __half* __restrict__ qkv, __half* __restrict__ o)
{
    int gw = blockIdx.x * 8 + (threadIdx.x >> 5);
    if (gw >= NN * NHEADS) return;
    int lane = threadIdx.x & 31;
    int n = gw >> 2;
    int h = gw & 3;

    float qf[VV][2], kf[VV][2], vf[VV][2];
#pragma unroll
    for (int l = 0; l < VV; l++) {
        long base = ((long)(l * NN + n)) * (3 * DD) + h * HD;
        qf[l][0] = __half2float(qkv[base + lane]);
        qf[l][1] = __half2float(qkv[base + lane + 32]);
        kf[l][0] = __half2float(qkv[base + DD + lane]);
        kf[l][1] = __half2float(qkv[base + DD + lane + 32]);
        vf[l][0] = __half2float(qkv[base + 2*DD + lane]);
        vf[l][1] = __half2float(qkv[base + 2*DD + lane + 32]);
    }

    float s[VV][VV];
#pragma unroll
    for (int l = 0; l < VV; l++)
#pragma unroll
        for (int m = 0; m < VV; m++) {
            float p = qf[l][0]*kf[m][0] + qf[l][1]*kf[m][1];
#pragma unroll
            for (int off = 16; off; off >>= 1)
                p += __shfl_xor_sync(0xFFFFFFFFu, p, off);
            s[l][m] = p * 0.125f;
        }

#pragma unroll
    for (int l = 0; l < VV; l++) {
        float mx = fmaxf(fmaxf(s[l][0], s[l][1]), fmaxf(s[l][2], s[l][3]));
        float e0 = __expf(s[l][0]-mx), e1 = __expf(s[l][1]-mx),
              e2 = __expf(s[l][2]-mx), e3 = __expf(s[l][3]-mx);
        float inv = 1.f / (e0+e1+e2+e3);
        float o0 = (e0*vf[0][0] + e1*vf[1][0] + e2*vf[2][0] + e3*vf[3][0]) * inv;
        float o1 = (e0*vf[0][1] + e1*vf[1][1] + e2*vf[2][1] + e3*vf[3][1]) * inv;
        long base = ((long)(l * NN + n)) * DD + h * HD;
        o[base + lane]      = __float2half_rn(o0);
        o[base + lane + 32] = __float2half_rn(o1);
    }
}

// ---------------- fast top-32 per off-diagonal (v,q,n) row of C -------------
__global__ __launch_bounds__(256)
void topk_fast(const float* __restrict__ C, int* __restrict__ outIdx)
{
    __shared__ unsigned long long buf[8][CAP];
    const unsigned FULL = 0xFFFFFFFFu;
    int wid = threadIdx.x >> 5, lane = threadIdx.x & 31;
    int gw = blockIdx.x * 8 + wid;
    int pair = gw / NN, n = gw - pair * NN;
    int v = pair / 3, r3 = pair - v * 3;
    int q = r3 + (r3 >= v ? 1 : 0);

    const float* row = C + ((long)(v*4 + q) * NN + n) * (long)NN;
    int* outp = outIdx + ((long)(v*4 + q) * NN + n) * TOPK;
    unsigned long long* wbuf = buf[wid];

    int cnt = 0;
    float thr = 0.95f;
#pragma unroll 1
    for (int att = 0; att < 2; att++) {
        cnt = 0;
#pragma unroll 1
        for (int i = lane; i < NN; i += 32) {
            float x = row[i];
            bool p = x > thr;
            unsigned m = __ballot_sync(FULL, p);
            if (p) {
                int pos = cnt + __popc(m & ((1u << lane) - 1u));
                if (pos < CAP)
                    wbuf[pos] = (((unsigned long long)__float_as_uint(x)) << 32)
                              | (unsigned)(0xFFFFFFFFu - i);
            }
            cnt += __popc(m);
        }
        if (cnt >= TOPK && cnt <= CAP) break;
        thr = 0.90f;
    }

    if (cnt < TOPK || cnt > CAP) {
        unsigned long long prev = 0xFFFFFFFFFFFFFFFFull;
        for (int j = 0; j < TOPK; j++) {
            unsigned long long best = 0;
            for (int i = lane; i < NN; i += 32) {
                unsigned b = __float_as_uint(row[i]);
                unsigned key32 = (b & 0x80000000u) ? ~b : (b | 0x80000000u);
                unsigned long long k =
                    (((unsigned long long)key32) << 32) | (unsigned)(0xFFFFFFFFu - i);
                if (k < prev && k > best) best = k;
            }
#pragma unroll
            for (int off = 16; off; off >>= 1) {
                unsigned long long o = __shfl_xor_sync(FULL, best, off);
                if (o > best) best = o;
            }
            if (lane == 0) outp[j] = (int)(0xFFFFFFFFu - (unsigned)best);
            prev = best;
        }
        return;
    }

    const int SL = CAP / 32;
    unsigned long long c[SL];
#pragma unroll
    for (int k = 0; k < SL; k++) {
        int j = lane + 32 * k;
        c[k] = (j < cnt) ? wbuf[j] : 0ull;
    }
    unsigned long long lmax = 0; int lslot = 0;
#pragma unroll
    for (int k = 0; k < SL; k++) if (c[k] > lmax) { lmax = c[k]; lslot = k; }

#pragma unroll 1
    for (int j = 0; j < TOPK; j++) {
        unsigned long long best = lmax;
#pragma unroll
        for (int off = 16; off; off >>= 1) {
            unsigned long long o = __shfl_xor_sync(FULL, best, off);
            if (o > best) best = o;
        }
        if (lmax == best && best != 0ull) {
            outp[j] = (int)(0xFFFFFFFFu - (unsigned)best);
            c[lslot] = 0ull;
            lmax = 0; lslot = 0;
#pragma unroll
            for (int k = 0; k < SL; k++) if (c[k] > lmax) { lmax = c[k]; lslot = k; }
        }
    }
}

// ---------------- Vn mean over tokens (p==q uniform-softmax term) ----------
__global__ void vmean_partial(const __half* __restrict__ Vh, float* __restrict__ part)
{
    int v = blockIdx.x, chunk = blockIdx.y, t = threadIdx.x;
    float s = 0.f;
    int nbeg = chunk * (NN/8), nend = nbeg + (NN/8);
    for (int n = nbeg; n < nend; n++)
        s += __half2float(Vh[((long)v * NN + n) * DD + t]);
    part[(v*8 + chunk) * DD + t] = s;
}
__global__ void vmean_final(const float* __restrict__ part, float* __restrict__ vmean)
{
    int v = blockIdx.x, t = threadIdx.x;
    float s = 0.f;
#pragma unroll
    for (int c = 0; c < 8; c++) s += part[(v*8 + c) * DD + t];
    vmean[v * DD + t] = s * (1.0f / NN);
}

// ---------------- sparse neighbor attention + final fuse -------------------
// One block per (p,n). V rows prefetched to smem via cp.async OVERLAPPED with
// the K dot phase; weighted sum then runs from smem.
#define NBR_SMEM (96*DD*2 + DD*4 + 96*4 + 96*4)

__global__ __launch_bounds__(256)
void nbr_out(const float* __restrict__ Qn, const __half* __restrict__ Kh,
             const __half* __restrict__ Vh, const float* __restrict__ vmean,
             const int* __restrict__ topk, const float* __restrict__ aligned,
             const float* __restrict__ Hin,
             const float* __restrict__ alpha_align, const float* __restrict__ beta,
             float* __restrict__ out)
{
    extern __shared__ __align__(16) char dsm[];
    __half* Vs   = reinterpret_cast<__half*>(dsm);                 // 96*DD halves
    float*  Qrow = reinterpret_cast<float*>(dsm + 96*DD*2);        // DD floats
    float*  sdots= reinterpret_cast<float*>(dsm + 96*DD*2 + DD*4); // 96
    int*    srow = reinterpret_cast<int*>(dsm + 96*DD*2 + DD*4 + 96*4);

    int pn = blockIdx.x;
    int p = pn / NN, n = pn % NN;
    int t = threadIdx.x, lane = t & 31, wid = t >> 5;

    long rowOff = (long)pn * DD;
    Qrow[t] = Qn[rowOff + t];
    if (t < 96) {
        int view = t >> 5;
        int q = view + (view >= p ? 1 : 0);
        int idx = topk[(((long)(p*VV + q)) * NN + n) * TOPK + (t & 31)];
        srow[t] = q * NN + idx;
    }
    float acc = vmean[p * DD + t];
    __syncthreads();

    // prefetch all 96 V rows (warp w owns rows w*12..w*12+11; lane = 16B chunk)
#pragma unroll
    for (int r = 0; r < 12; r++) {
        int j = wid * 12 + r;
        cp16(&Vs[j * DD + lane * 8], &Vh[(long)srow[j] * DD + lane * 8]);
    }
    cp_commit();

    // K dots for the same 12 rows, 4-wide load batches for MLP
    float4 qa = *reinterpret_cast<const float4*>(&Qrow[lane*8]);
    float4 qb = *reinterpret_cast<const float4*>(&Qrow[lane*8+4]);
#pragma unroll
    for (int r = 0; r < 12; r += 4) {
        uint4 kv[4];
#pragma unroll
        for (int u = 0; u < 4; u++)
            kv[u] = *reinterpret_cast<const uint4*>(
                Kh + (long)srow[wid*12 + r + u] * DD + lane * 8);
#pragma unroll
        for (int u = 0; u < 4; u++) {
            float2 k0 = __half22float2(*reinterpret_cast<__half2*>(&kv[u].x));
            float2 k1 = __half22float2(*reinterpret_cast<__half2*>(&kv[u].y));
            float2 k2 = __half22float2(*reinterpret_cast<__half2*>(&kv[u].z));
            float2 k3 = __half22float2(*reinterpret_cast<__half2*>(&kv[u].w));
            float psum = qa.x*k0.x + qa.y*k0.y + qa.z*k1.x + qa.w*k1.y
                       + qb.x*k2.x + qb.y*k2.y + qb.z*k3.x + qb.w*k3.y;
#pragma unroll
            for (int off = 16; off; off >>= 1)
                psum += __shfl_xor_sync(0xFFFFFFFFu, psum, off);
            if (lane == 0) sdots[wid*12 + r + u] = psum * 0.0625f;
        }
    }
    __syncthreads();

    // 3 parallel softmaxes (one view per warp)
    if (wid < 3) {
        float x = sdots[wid*32 + lane];
        float mx = x;
#pragma unroll
        for (int off = 16; off; off >>= 1)
            mx = fmaxf(mx, __shfl_xor_sync(0xFFFFFFFFu, mx, off));
        float e = __expf(x - mx);
        float sm = e;
#pragma unroll
        for (int off = 16; off; off >>= 1)
            sm += __shfl_xor_sync(0xFFFFFFFFu, sm, off);
        sdots[wid*32 + lane] = e / sm;
    }
    cp_wait<0>();
    __syncthreads();

    // weighted V accumulation from smem
    float a1 = 0.f;
#pragma unroll 8
    for (int j = 0; j < 96; j += 2) {
        acc = fmaf(sdots[j],   __half2float(Vs[j*DD + t]),     acc);
        a1  = fmaf(sdots[j+1], __half2float(Vs[(j+1)*DD + t]), a1);
    }
    acc += a1;

    float aa = 1.f / (1.f + __expf(-alpha_align[0]));
    float bb = 1.f / (1.f + __expf(-beta[0]));
    float al = aligned[rowOff + t];
    float f  = fmaxf(aa * al + (1.f - aa) * acc, 0.f);
    out[rowOff + t] = bb * Hin[rowOff + t] + (1.f - bb) * f;
}

// ---------------- launch ----------------------------------------------------
extern "C" void kernel_launch(void* const* d_in, const int* in_sizes, int n_in,
                              void* d_out, int out_size)
{
    const float* H      = (const float*)d_in[0];
    const float* C      = (const float*)d_in[1];
    const float* WQ     = (const float*)d_in[2];
    const float* WK     = (const float*)d_in[3];
    const float* WV     = (const float*)d_in[4];
    const float* ipw    = (const float*)d_in[5];
    const float* ipb    = (const float*)d_in[6];
    const float* ow     = (const float*)d_in[7];
    const float* ob     = (const float*)d_in[8];
    const float* alphas = (const float*)d_in[9];
    const float* aal    = (const float*)d_in[10];
    const float* bet    = (const float*)d_in[11];
    float* out = (float*)d_out;

    __half *p_Hh, *p_ipwh, *p_owh, *p_WQh, *p_WKh, *p_WVh;
    __half *p_qkvh, *p_oh, *p_alignedh, *p_Kh, *p_Vh;
    float *p_aligned, *p_Qn, *p_part, *p_vmean;
    int* p_tk;
    cudaGetSymbolAddress((void**)&p_Hh, g_Hh);
    cudaGetSymbolAddress((void**)&p_ipwh, g_ipwh);
    cudaGetSymbolAddress((void**)&p_owh, g_owh);
    cudaGetSymbolAddress((void**)&p_WQh, g_WQh);
    cudaGetSymbolAddress((void**)&p_WKh, g_WKh);
    cudaGetSymbolAddress((void**)&p_WVh, g_WVh);
    cudaGetSymbolAddress((void**)&p_qkvh, g_qkvh);
    cudaGetSymbolAddress((void**)&p_oh, g_oh);
    cudaGetSymbolAddress((void**)&p_aligned, g_aligned);
    cudaGetSymbolAddress((void**)&p_alignedh, g_alignedh);
    cudaGetSymbolAddress((void**)&p_Qn, g_Qn);
    cudaGetSymbolAddress((void**)&p_Kh, g_Kh);
    cudaGetSymbolAddress((void**)&p_Vh, g_Vh);
    cudaGetSymbolAddress((void**)&p_part, g_part);
    cudaGetSymbolAddress((void**)&p_vmean, g_vmean);
    cudaGetSymbolAddress((void**)&p_tk, g_topk);

    // one-time infra (streams/events); attrs set idempotently every call
    static cudaStream_t sB = nullptr, sC = nullptr;
    static cudaEvent_t evRoot = nullptr, evB = nullptr, evC = nullptr;
    if (sB == nullptr) {
        cudaStreamCreateWithFlags(&sB, cudaStreamNonBlocking);
        cudaStreamCreateWithFlags(&sC, cudaStreamNonBlocking);
        cudaEventCreateWithFlags(&evRoot, cudaEventDisableTiming);
        cudaEventCreateWithFlags(&evB, cudaEventDisableTiming);
        cudaEventCreateWithFlags(&evC, cudaEventDisableTiming);
    }
    cudaFuncSetAttribute(hgemm<0>, cudaFuncAttributeMaxDynamicSharedMemorySize, HG_SMEM);
    cudaFuncSetAttribute(hgemm<1>, cudaFuncAttributeMaxDynamicSharedMemorySize, HG_SMEM);
    cudaFuncSetAttribute(hgemm<2>, cudaFuncAttributeMaxDynamicSharedMemorySize, HG_SMEM);
    cudaFuncSetAttribute(nbr_out, cudaFuncAttributeMaxDynamicSharedMemorySize, NBR_SMEM);

    auto cgrid = [](int n){ return (n/8 + 255) / 256; };

    // fork side streams off the capture stream
    cudaEventRecord(evRoot, 0);
    cudaStreamWaitEvent(sB, evRoot, 0);
    cudaStreamWaitEvent(sC, evRoot, 0);

    // side stream B: top-k over C (independent, HBM-bound)
    topk_fast<<<(12 * NN) / 8, 256, 0, sB>>>(C, p_tk);
    cudaEventRecord(evB, sB);

    // side stream C: weight conversions not needed until hgemm1/hgemm2
    f2h<<<cgrid(DD*DD), 256, 0, sC>>>(ow, p_owh, DD*DD);
    f2h<<<cgrid(VV*DD*DD), 256, 0, sC>>>(WQ, p_WQh, VV*DD*DD);
    f2h<<<cgrid(VV*DD*DD), 256, 0, sC>>>(WK, p_WKh, VV*DD*DD);
    f2h<<<cgrid(VV*DD*DD), 256, 0, sC>>>(WV, p_WVh, VV*DD*DD);
    cudaEventRecord(evC, sC);

    // main chain
    f2h<<<cgrid(ROWS_TOT*DD), 256>>>(H, p_Hh, ROWS_TOT*DD);
    f2h<<<cgrid(3*DD*DD), 256>>>(ipw, p_ipwh, 3*DD*DD);

    // 1) qkv(f16) = H @ in_proj_w^T + b
    hgemm<0><<<dim3(768/128, ROWS_TOT/64), 256, HG_SMEM>>>(
        p_Hh, p_ipwh, nullptr, nullptr, ipb, nullptr, nullptr,
        nullptr, p_qkvh, nullptr, nullptr, 3*DD);

    // 2) tiny 4x4 attention over views -> o (fp16)
    view_attn<<<(NN*NHEADS)/8, 256>>>(p_qkvh, p_oh);

    cudaStreamWaitEvent(0, evC, 0);   // join weight converts

    // 3) aligned = a*(o @ out_w^T + b) + (1-a)*H   (f32 + f16 copies)
    hgemm<1><<<dim3(DD/128, ROWS_TOT/64), 256, HG_SMEM>>>(
        p_oh, p_owh, nullptr, nullptr, ob, H, alphas,
        p_aligned, p_alignedh, nullptr, nullptr, DD);

    // 4) fused per-view Qn(f32)/Kh/Vh
    hgemm<2><<<dim3(DD/128, NN/64, 12), 256, HG_SMEM>>>(
        p_alignedh, p_WQh, p_WKh, p_WVh, nullptr, nullptr, nullptr,
        p_Qn, nullptr, p_Kh, p_Vh, DD);

    // 5) mean of Vn over tokens
    vmean_partial<<<dim3(VV, 8), 256>>>(p_Vh, p_part);
    vmean_final<<<VV, 256>>>(p_part, p_vmean);

    cudaStreamWaitEvent(0, evB, 0);   // join top-k

    // 6) sparse neighbor attention + final relu/fuse
    nbr_out<<<ROWS_TOT, 256, NBR_SMEM>>>(p_Qn, p_Kh, p_Vh, p_vmean, p_tk,
                                         p_aligned, H, aal, bet, out);
}